// round 1
// baseline (speedup 1.0000x reference)
#include <cuda_runtime.h>
#include <cuda_bf16.h>
#include <math.h>

// ---------------------------------------------------------------------------
// MLA attention, fp32 baseline.
// B=4, T=2048, C=1024, H=16, HS=64, DHR=32, D=HS+DHR=96, M=B*T=8192
// ---------------------------------------------------------------------------

#define Bb   4
#define Tt   2048
#define Cc_  1024
#define Hh   16
#define HS_  64
#define DHR_ 32
#define Dd   96
#define MM   (Bb*Tt)          // 8192
#define BH   (Bb*Hh)          // 64

// ------------------------- scratch (static device) -------------------------
__device__ float g_cQ [(size_t)MM*4096];
__device__ float g_cKV[(size_t)MM*256];
__device__ float g_qC [(size_t)MM*1024];
__device__ float g_kC [(size_t)MM*1024];
__device__ float g_v  [(size_t)MM*1024];
__device__ float g_qR [(size_t)MM*512];
__device__ float g_kR [(size_t)MM*32];
__device__ float g_Q  [(size_t)BH*Tt*Dd];
__device__ float g_K  [(size_t)BH*Tt*Dd];
__device__ float g_V  [(size_t)BH*Tt*HS_];
__device__ float g_S  [(size_t)BH*Tt*Tt];
__device__ float g_Y  [(size_t)MM*1024];

// ------------------------- generic tiled SGEMM -----------------------------
// C = A(MxK) * B(KxN)   (TRB=false, B row-major KxN)
// C = A(MxK) * B(NxK)^T (TRB=true,  B row-major NxK)
// Batched over blockIdx.z with linear strides sA,sB; C offset is
// (z/Hdiv)*cB + (z%Hdiv)*cH, row stride ldc (covers the strided PV epilogue).
template<int BM,int BN,int BK,int TM,int TN,bool TRB>
__global__ void gemm_kernel(const float* __restrict__ A,
                            const float* __restrict__ B,
                            float* __restrict__ C,
                            int M, int N, int K,
                            long long sA, long long sB,
                            long long cB, long long cH, int Hdiv, int ldc)
{
    constexpr int THREADS = (BM/TM)*(BN/TN);
    __shared__ float As[BK][BM];
    __shared__ float Bs[BK][BN];

    const int z = blockIdx.z;
    A += (long long)z * sA;
    B += (long long)z * sB;
    C += (long long)(z / Hdiv) * cB + (long long)(z % Hdiv) * cH;

    const int tid = threadIdx.x;
    const int bm  = blockIdx.y * BM;
    const int bn  = blockIdx.x * BN;
    const int tx  = tid % (BN/TN);
    const int ty  = tid / (BN/TN);

    float acc[TM][TN];
    #pragma unroll
    for (int i = 0; i < TM; i++)
        #pragma unroll
        for (int j = 0; j < TN; j++) acc[i][j] = 0.f;

    for (int k0 = 0; k0 < K; k0 += BK) {
        // load A tile (BM x BK), store transposed As[k][m]
        #pragma unroll
        for (int i = tid*4; i < BM*BK; i += THREADS*4) {
            int row = i / BK;
            int kc  = i % BK;
            float4 v = *(const float4*)(A + (long long)(bm+row)*K + k0 + kc);
            As[kc+0][row] = v.x; As[kc+1][row] = v.y;
            As[kc+2][row] = v.z; As[kc+3][row] = v.w;
        }
        if (!TRB) {
            // load B tile (BK x BN) row-major
            #pragma unroll
            for (int i = tid*4; i < BK*BN; i += THREADS*4) {
                int row = i / BN;   // k
                int col = i % BN;   // n
                float4 v = *(const float4*)(B + (long long)(k0+row)*N + bn + col);
                *(float4*)&Bs[row][col] = v;
            }
        } else {
            // load B tile from (N x K): rows are n, cols are k; store Bs[k][n]
            #pragma unroll
            for (int i = tid*4; i < BN*BK; i += THREADS*4) {
                int row = i / BK;   // n
                int kc  = i % BK;   // k
                float4 v = *(const float4*)(B + (long long)(bn+row)*K + k0 + kc);
                Bs[kc+0][row] = v.x; Bs[kc+1][row] = v.y;
                Bs[kc+2][row] = v.z; Bs[kc+3][row] = v.w;
            }
        }
        __syncthreads();

        #pragma unroll
        for (int kk = 0; kk < BK; kk++) {
            float a[TM], b[TN];
            #pragma unroll
            for (int i = 0; i < TM; i++) a[i] = As[kk][ty*TM+i];
            #pragma unroll
            for (int j = 0; j < TN; j++) b[j] = Bs[kk][tx*TN+j];
            #pragma unroll
            for (int i = 0; i < TM; i++)
                #pragma unroll
                for (int j = 0; j < TN; j++) acc[i][j] += a[i]*b[j];
        }
        __syncthreads();
    }

    #pragma unroll
    for (int i = 0; i < TM; i++) {
        long long rowoff = (long long)(bm + ty*TM + i) * ldc + bn + tx*TN;
        #pragma unroll
        for (int j = 0; j < TN; j++) C[rowoff + j] = acc[i][j];
    }
}

// ------------------------- small-N GEMM (k_R, N=32) ------------------------
__global__ void gemm_n32(const float* __restrict__ A, const float* __restrict__ Bw,
                         float* __restrict__ Cm, int M, int K)
{
    int gw   = (blockIdx.x * blockDim.x + threadIdx.x) >> 5;
    int lane = threadIdx.x & 31;
    if (gw >= M) return;
    const float* a = A + (long long)gw * K;
    float acc = 0.f;
    #pragma unroll 8
    for (int k = 0; k < K; k++)
        acc += a[k] * Bw[k*32 + lane];
    Cm[(long long)gw*32 + lane] = acc;
}

// --------------------- assemble Q/K/V with RoPE scale ----------------------
// Q,K : (B,H,T,96)   V : (B,H,T,64)
__global__ void assemble_qkv(const float* __restrict__ qC, const float* __restrict__ qR,
                             const float* __restrict__ kC, const float* __restrict__ kR,
                             const float* __restrict__ vr,
                             float* __restrict__ Q, float* __restrict__ K,
                             float* __restrict__ V)
{
    const long long total = (long long)BH * Tt * Dd;
    for (long long idx = (long long)blockIdx.x * blockDim.x + threadIdx.x;
         idx < total; idx += (long long)gridDim.x * blockDim.x)
    {
        int d = (int)(idx % Dd);
        long long r = idx / Dd;            // (b,h,t)
        int t = (int)(r % Tt);
        long long r2 = r / Tt;             // (b,h)
        int h = (int)(r2 % Hh);
        int b = (int)(r2 / Hh);
        long long bt = (long long)b * Tt + t;

        float qv, kv;
        if (d < HS_) {
            long long src = bt * 1024 + h * HS_ + d;
            qv = qC[src];
            kv = kC[src];
            V[(r2 * Tt + t) * HS_ + d] = vr[src];
        } else {
            int j  = d - HS_;
            int fi = j & 15;
            // inv = 10000^{-fi/16}; scale = cos(t*inv)+sin(t*inv)
            double inv = exp(-(double)fi * 0.57564627324851148);  // ln(10000)/16
            double ang = (double)t * inv;
            float sc = (float)(cos(ang) + sin(ang));
            qv = qR[bt * 512 + h * DHR_ + j] * sc;
            kv = kR[bt * 32 + j] * sc;
        }
        Q[idx] = qv;
        K[idx] = kv;
    }
}

// ------------------------- causal softmax (rows of S) ----------------------
__global__ void softmax_causal(float* __restrict__ S, float scale)
{
    const int VPT = Tt / 256;              // 8
    long long r = blockIdx.x;              // (b*H+h)*T + q
    int q = (int)(r % Tt);
    float* row = S + r * Tt;
    int tid = threadIdx.x;

    float vals[VPT];
    float mx = -1e30f;
    #pragma unroll
    for (int i = 0; i < VPT; i++) {
        int c = tid + i*256;
        float v = row[c] * scale;
        vals[i] = (c <= q) ? v : -1e30f;
        mx = fmaxf(mx, vals[i]);
    }

    __shared__ float red[8];
    // block max
    #pragma unroll
    for (int o = 16; o > 0; o >>= 1) mx = fmaxf(mx, __shfl_xor_sync(0xffffffffu, mx, o));
    if ((tid & 31) == 0) red[tid >> 5] = mx;
    __syncthreads();
    if (tid < 32) {
        float v = (tid < 8) ? red[tid] : -1e30f;
        #pragma unroll
        for (int o = 4; o > 0; o >>= 1) v = fmaxf(v, __shfl_xor_sync(0xffffffffu, v, o));
        if (tid == 0) red[0] = v;
    }
    __syncthreads();
    mx = red[0];
    __syncthreads();

    float s = 0.f;
    #pragma unroll
    for (int i = 0; i < VPT; i++) {
        float p = (vals[i] > -1e29f) ? expf(vals[i] - mx) : 0.f;
        vals[i] = p;
        s += p;
    }
    // block sum
    #pragma unroll
    for (int o = 16; o > 0; o >>= 1) s += __shfl_xor_sync(0xffffffffu, s, o);
    if ((tid & 31) == 0) red[tid >> 5] = s;
    __syncthreads();
    if (tid < 32) {
        float v = (tid < 8) ? red[tid] : 0.f;
        #pragma unroll
        for (int o = 4; o > 0; o >>= 1) v += __shfl_xor_sync(0xffffffffu, v, o);
        if (tid == 0) red[0] = v;
    }
    __syncthreads();
    float invs = 1.f / red[0];

    #pragma unroll
    for (int i = 0; i < VPT; i++)
        row[tid + i*256] = vals[i] * invs;
}

// ---------------------------------------------------------------------------
extern "C" void kernel_launch(void* const* d_in, const int* in_sizes, int n_in,
                              void* d_out, int out_size)
{
    const float* x     = (const float*)d_in[0];
    const float* W_DQ  = (const float*)d_in[1];
    const float* W_UQ  = (const float*)d_in[2];
    const float* W_DKV = (const float*)d_in[3];
    const float* W_UK  = (const float*)d_in[4];
    const float* W_UV  = (const float*)d_in[5];
    const float* W_QR  = (const float*)d_in[6];
    const float* W_KR  = (const float*)d_in[7];
    const float* W_O   = (const float*)d_in[8];
    float* out = (float*)d_out;

    float *cQ, *cKV, *qC, *kC, *v, *qR, *kR, *Q, *K, *V, *S, *Y;
    cudaGetSymbolAddress((void**)&cQ,  g_cQ);
    cudaGetSymbolAddress((void**)&cKV, g_cKV);
    cudaGetSymbolAddress((void**)&qC,  g_qC);
    cudaGetSymbolAddress((void**)&kC,  g_kC);
    cudaGetSymbolAddress((void**)&v,   g_v);
    cudaGetSymbolAddress((void**)&qR,  g_qR);
    cudaGetSymbolAddress((void**)&kR,  g_kR);
    cudaGetSymbolAddress((void**)&Q,   g_Q);
    cudaGetSymbolAddress((void**)&K,   g_K);
    cudaGetSymbolAddress((void**)&V,   g_V);
    cudaGetSymbolAddress((void**)&S,   g_S);
    cudaGetSymbolAddress((void**)&Y,   g_Y);

    // 1. cQ = x @ W_DQ              (8192, 4096, 1024)
    gemm_kernel<128,128,16,8,8,false><<<dim3(4096/128, MM/128, 1), 256>>>(
        x, W_DQ, cQ, MM, 4096, 1024, 0, 0, 0, 0, 1, 4096);
    // 2. qC = cQ @ W_UQ             (8192, 1024, 4096)
    gemm_kernel<128,128,16,8,8,false><<<dim3(1024/128, MM/128, 1), 256>>>(
        cQ, W_UQ, qC, MM, 1024, 4096, 0, 0, 0, 0, 1, 1024);
    // 3. cKV = x @ W_DKV            (8192, 256, 1024)
    gemm_kernel<128,128,16,8,8,false><<<dim3(256/128, MM/128, 1), 256>>>(
        x, W_DKV, cKV, MM, 256, 1024, 0, 0, 0, 0, 1, 256);
    // 4. kC = cKV @ W_UK            (8192, 1024, 256)
    gemm_kernel<128,128,16,8,8,false><<<dim3(1024/128, MM/128, 1), 256>>>(
        cKV, W_UK, kC, MM, 1024, 256, 0, 0, 0, 0, 1, 1024);
    // 5. v = cKV @ W_UV             (8192, 1024, 256)
    gemm_kernel<128,128,16,8,8,false><<<dim3(1024/128, MM/128, 1), 256>>>(
        cKV, W_UV, v, MM, 1024, 256, 0, 0, 0, 0, 1, 1024);
    // 6. qR = cQ @ W_QR             (8192, 512, 4096)
    gemm_kernel<128,128,16,8,8,false><<<dim3(512/128, MM/128, 1), 256>>>(
        cQ, W_QR, qR, MM, 512, 4096, 0, 0, 0, 0, 1, 512);
    // 7. kR = x @ W_KR              (8192, 32, 1024)
    gemm_n32<<<(MM*32)/256, 256>>>(x, W_KR, kR, MM, 1024);

    // 8. assemble Q/K/V with RoPE scale
    {
        long long total = (long long)BH * Tt * Dd;
        int blocks = (int)((total + 255) / 256);
        assemble_qkv<<<blocks, 256>>>(qC, qR, kC, kR, v, Q, K, V);
    }

    // 9. S = Q @ K^T  batched over 64 (b,h)   (2048, 2048, 96)
    gemm_kernel<128,128,16,8,8,true><<<dim3(Tt/128, Tt/128, BH), 256>>>(
        Q, K, S, Tt, Tt, Dd,
        (long long)Tt*Dd, (long long)Tt*Dd,
        (long long)Tt*Tt, 0, 1, Tt);

    // 10. causal softmax over rows of S
    softmax_causal<<<BH*Tt, 256>>>(S, 1.0f / sqrtf((float)Dd));

    // 11. Y = P @ V  batched, writes directly into (B,T,H*HS) layout
    gemm_kernel<128,64,16,8,4,false><<<dim3(1, Tt/128, BH), 256>>>(
        S, V, Y, Tt, HS_, Tt,
        (long long)Tt*Tt, (long long)Tt*HS_,
        (long long)Tt*Cc_, (long long)HS_, Hh, Cc_);

    // 12. out = Y @ W_O             (8192, 1024, 1024)
    gemm_kernel<128,128,16,8,8,false><<<dim3(1024/128, MM/128, 1), 256>>>(
        Y, W_O, out, MM, 1024, 1024, 0, 0, 0, 0, 1, 1024);
}

// round 4
// speedup vs baseline: 2.0430x; 2.0430x over previous
#include <cuda_runtime.h>
#include <cuda_bf16.h>
#include <math.h>
#include <stdint.h>

// ---------------------------------------------------------------------------
// MLA attention, TF32 tensor-core version (mma.sync.m16n8k8.tf32).
// B=4, T=2048, C=1024, H=16, HS=64, DHR=32, D=HS+DHR=96, M=B*T=8192
// ---------------------------------------------------------------------------

#define Bb   4
#define Tt   2048
#define Cc_  1024
#define Hh   16
#define HS_  64
#define DHR_ 32
#define Dd   96
#define MM   (Bb*Tt)          // 8192
#define BH   (Bb*Hh)          // 64

// ------------------------- scratch (static device) -------------------------
__device__ float g_cQ [(size_t)MM*4096];
__device__ float g_cKV[(size_t)MM*256];
__device__ float g_qC [(size_t)MM*1024];
__device__ float g_kC [(size_t)MM*1024];
__device__ float g_v  [(size_t)MM*1024];
__device__ float g_qR [(size_t)MM*512];
__device__ float g_kR [(size_t)MM*32];
__device__ float g_Q  [(size_t)BH*Tt*Dd];
__device__ float g_K  [(size_t)BH*Tt*Dd];
__device__ float g_V  [(size_t)BH*Tt*HS_];
__device__ float g_S  [(size_t)BH*Tt*Tt];
__device__ float g_Y  [(size_t)MM*1024];

// ------------------------- helpers -----------------------------------------
__device__ __forceinline__ float to_tf32(float f) {
    uint32_t u;
    asm("cvt.rna.tf32.f32 %0, %1;" : "=r"(u) : "f"(f));
    return __uint_as_float(u);
}

__device__ __forceinline__ void mma_tf32(float* c, const uint32_t* a, const uint32_t* b) {
    asm volatile(
        "mma.sync.aligned.m16n8k8.row.col.f32.tf32.tf32.f32 "
        "{%0,%1,%2,%3}, {%4,%5,%6,%7}, {%8,%9}, {%0,%1,%2,%3};"
        : "+f"(c[0]), "+f"(c[1]), "+f"(c[2]), "+f"(c[3])
        : "r"(a[0]), "r"(a[1]), "r"(a[2]), "r"(a[3]),
          "r"(b[0]), "r"(b[1]));
}

// ------------------------- TF32 tensor-core GEMM ---------------------------
// C = A(MxK) * B(KxN)   (TRB=false)
// C = A(MxK) * B(NxK)^T (TRB=true)
// Batched over blockIdx.z with strides sA, sB; C offset is
// (z/Hdiv)*cB + (z%Hdiv)*cH, row stride ldc.
// CAUSAL: for TRB (QK^T) skip fully-masked tiles; for !TRB (PV) bound k-loop.
template<int BM,int BN,int BK,int WM,int WN,bool TRB,bool CAUSAL>
__global__ void __launch_bounds__(256, 1)
gemm_tc(const float* __restrict__ A,
        const float* __restrict__ B,
        float* __restrict__ C,
        int M, int N, int K,
        long long sA, long long sB,
        long long cB, long long cH, int Hdiv, int ldc)
{
    constexpr int WARPS_N = BN/WN;
    constexpr int WARPS   = (BM/WM)*WARPS_N;
    constexpr int THREADS = WARPS*32;
    constexpr int MT = WM/16;
    constexpr int NT = WN/8;

    const int bm = blockIdx.y * BM;
    const int bn = blockIdx.x * BN;
    if (CAUSAL && TRB && bn > bm + BM - 1) return;   // fully masked S tile

    __shared__ float As[BK][BM+8];
    __shared__ float Bs[BK][BN+8];

    const int z = blockIdx.z;
    A += (long long)z * sA;
    B += (long long)z * sB;
    C += (long long)(z / Hdiv) * cB + (long long)(z % Hdiv) * cH;

    const int tid  = threadIdx.x;
    const int warp = tid >> 5;
    const int lane = tid & 31;
    const int lr   = lane >> 2;   // 0..7
    const int lc   = lane & 3;    // 0..3
    const int wm0  = (warp / WARPS_N) * WM;
    const int wn0  = (warp % WARPS_N) * WN;

    float acc[MT][NT][4];
    #pragma unroll
    for (int i = 0; i < MT; i++)
        #pragma unroll
        for (int j = 0; j < NT; j++)
            #pragma unroll
            for (int r = 0; r < 4; r++) acc[i][j][r] = 0.f;

    const int kend = (CAUSAL && !TRB) ? min(K, bm + BM) : K;

    for (int k0 = 0; k0 < kend; k0 += BK) {
        // --- load A tile (BM x BK), store transposed As[k][m], tf32-rounded
        #pragma unroll
        for (int i = tid*4; i < BM*BK; i += THREADS*4) {
            int m  = i / BK;
            int kc = i % BK;
            float4 v = *(const float4*)(A + (long long)(bm+m)*K + k0 + kc);
            As[kc+0][m] = to_tf32(v.x); As[kc+1][m] = to_tf32(v.y);
            As[kc+2][m] = to_tf32(v.z); As[kc+3][m] = to_tf32(v.w);
        }
        if (!TRB) {
            #pragma unroll
            for (int i = tid*4; i < BK*BN; i += THREADS*4) {
                int kr = i / BN;
                int nc = i % BN;
                float4 v = *(const float4*)(B + (long long)(k0+kr)*N + bn + nc);
                Bs[kr][nc+0] = to_tf32(v.x); Bs[kr][nc+1] = to_tf32(v.y);
                Bs[kr][nc+2] = to_tf32(v.z); Bs[kr][nc+3] = to_tf32(v.w);
            }
        } else {
            #pragma unroll
            for (int i = tid*4; i < BN*BK; i += THREADS*4) {
                int nr = i / BK;
                int kc = i % BK;
                float4 v = *(const float4*)(B + (long long)(bn+nr)*K + k0 + kc);
                Bs[kc+0][nr] = to_tf32(v.x); Bs[kc+1][nr] = to_tf32(v.y);
                Bs[kc+2][nr] = to_tf32(v.z); Bs[kc+3][nr] = to_tf32(v.w);
            }
        }
        __syncthreads();

        #pragma unroll
        for (int kk = 0; kk < BK; kk += 8) {
            uint32_t a[MT][4], b[NT][2];
            #pragma unroll
            for (int mt = 0; mt < MT; mt++) {
                int m = wm0 + mt*16 + lr;
                a[mt][0] = __float_as_uint(As[kk+lc  ][m  ]);
                a[mt][1] = __float_as_uint(As[kk+lc  ][m+8]);
                a[mt][2] = __float_as_uint(As[kk+lc+4][m  ]);
                a[mt][3] = __float_as_uint(As[kk+lc+4][m+8]);
            }
            #pragma unroll
            for (int nt = 0; nt < NT; nt++) {
                int n = wn0 + nt*8 + lr;
                b[nt][0] = __float_as_uint(Bs[kk+lc  ][n]);
                b[nt][1] = __float_as_uint(Bs[kk+lc+4][n]);
            }
            #pragma unroll
            for (int mt = 0; mt < MT; mt++)
                #pragma unroll
                for (int nt = 0; nt < NT; nt++)
                    mma_tf32(acc[mt][nt], a[mt], b[nt]);
        }
        __syncthreads();
    }

    // --- store (float2 per row-pair) ---
    #pragma unroll
    for (int mt = 0; mt < MT; mt++) {
        int row0 = bm + wm0 + mt*16 + lr;
        #pragma unroll
        for (int nt = 0; nt < NT; nt++) {
            int col = bn + wn0 + nt*8 + 2*lc;
            float2 v0 = make_float2(acc[mt][nt][0], acc[mt][nt][1]);
            float2 v1 = make_float2(acc[mt][nt][2], acc[mt][nt][3]);
            *(float2*)(C + (long long)row0*ldc + col)     = v0;
            *(float2*)(C + (long long)(row0+8)*ldc + col) = v1;
        }
    }
}

// ------------------------- small-N GEMM (k_R, N=32) ------------------------
__global__ void gemm_n32(const float* __restrict__ A, const float* __restrict__ Bw,
                         float* __restrict__ Cm, int M, int K)
{
    int gw   = (blockIdx.x * blockDim.x + threadIdx.x) >> 5;
    int lane = threadIdx.x & 31;
    if (gw >= M) return;
    const float* a = A + (long long)gw * K;
    float acc = 0.f;
    #pragma unroll 8
    for (int k = 0; k < K; k++)
        acc += a[k] * Bw[k*32 + lane];
    Cm[(long long)gw*32 + lane] = acc;
}

// --------------------- assemble Q/K/V with RoPE scale ----------------------
__constant__ float c_inv[16] = {
    1.0f, 0.5623413251903491f, 0.31622776601683794f, 0.17782794100389228f,
    0.1f, 0.05623413251903491f, 0.031622776601683794f, 0.017782794100389228f,
    0.01f, 0.005623413251903491f, 0.0031622776601683794f, 0.0017782794100389228f,
    0.001f, 0.0005623413251903491f, 0.00031622776601683794f, 0.00017782794100389228f
};

__global__ void assemble_qkv(const float* __restrict__ qC, const float* __restrict__ qR,
                             const float* __restrict__ kC, const float* __restrict__ kR,
                             const float* __restrict__ vr,
                             float* __restrict__ Q, float* __restrict__ K,
                             float* __restrict__ V)
{
    const long long total = (long long)BH * Tt * Dd;
    for (long long idx = (long long)blockIdx.x * blockDim.x + threadIdx.x;
         idx < total; idx += (long long)gridDim.x * blockDim.x)
    {
        int d = (int)(idx % Dd);
        long long r = idx / Dd;            // (b,h,t)
        int t = (int)(r % Tt);
        long long r2 = r / Tt;             // (b,h)
        int h = (int)(r2 % Hh);
        int b = (int)(r2 / Hh);
        long long bt = (long long)b * Tt + t;

        float qv, kv;
        if (d < HS_) {
            long long src = bt * 1024 + h * HS_ + d;
            qv = qC[src];
            kv = kC[src];
            V[(r2 * Tt + t) * HS_ + d] = vr[src];
        } else {
            int j  = d - HS_;
            int fi = j & 15;
            float ang = (float)t * c_inv[fi];
            float s_, co;
            sincosf(ang, &s_, &co);
            float sc = co + s_;
            qv = qR[bt * 512 + h * DHR_ + j] * sc;
            kv = kR[bt * 32 + j] * sc;
        }
        Q[idx] = qv;
        K[idx] = kv;
    }
}

// ------------------- causal softmax (rows of S, truncated) -----------------
// Processes only columns [0, qb_end) where qb_end = round-up-128(q+1);
// zeroes masked entries inside the diagonal block so PV can read them.
__global__ void softmax_causal(float* __restrict__ S, float scale)
{
    long long r = blockIdx.x;              // (b*H+h)*T + q
    int q = (int)(r % Tt);
    int qb_end = ((q >> 7) + 1) << 7;      // multiple of 128
    float* row = S + r * Tt;
    int tid = threadIdx.x;

    float vals[8];
    #pragma unroll
    for (int i = 0; i < 8; i++) vals[i] = -1e30f;

    float mx = -1e30f;
    for (int i = 0; i*256 < qb_end; i++) {
        int c = tid + i*256;
        if (c < qb_end) {
            float v = (c <= q) ? row[c]*scale : -1e30f;
            vals[i] = v;
            mx = fmaxf(mx, v);
        }
    }

    __shared__ float red[8];
    #pragma unroll
    for (int o = 16; o > 0; o >>= 1) mx = fmaxf(mx, __shfl_xor_sync(0xffffffffu, mx, o));
    if ((tid & 31) == 0) red[tid >> 5] = mx;
    __syncthreads();
    if (tid < 32) {
        float v = (tid < 8) ? red[tid] : -1e30f;
        #pragma unroll
        for (int o = 4; o > 0; o >>= 1) v = fmaxf(v, __shfl_xor_sync(0xffffffffu, v, o));
        if (tid == 0) red[0] = v;
    }
    __syncthreads();
    mx = red[0];
    __syncthreads();

    float s = 0.f;
    for (int i = 0; i*256 < qb_end; i++) {
        int c = tid + i*256;
        if (c < qb_end) {
            float p = (vals[i] > -1e29f) ? expf(vals[i] - mx) : 0.f;
            vals[i] = p;
            s += p;
        }
    }
    #pragma unroll
    for (int o = 16; o > 0; o >>= 1) s += __shfl_xor_sync(0xffffffffu, s, o);
    if ((tid & 31) == 0) red[tid >> 5] = s;
    __syncthreads();
    if (tid < 32) {
        float v = (tid < 8) ? red[tid] : 0.f;
        #pragma unroll
        for (int o = 4; o > 0; o >>= 1) v += __shfl_xor_sync(0xffffffffu, v, o);
        if (tid == 0) red[0] = v;
    }
    __syncthreads();
    float invs = 1.f / red[0];

    for (int i = 0; i*256 < qb_end; i++) {
        int c = tid + i*256;
        if (c < qb_end)
            row[c] = (c <= q) ? vals[i] * invs : 0.f;
    }
}

// ---------------------------------------------------------------------------
extern "C" void kernel_launch(void* const* d_in, const int* in_sizes, int n_in,
                              void* d_out, int out_size)
{
    const float* x     = (const float*)d_in[0];
    const float* W_DQ  = (const float*)d_in[1];
    const float* W_UQ  = (const float*)d_in[2];
    const float* W_DKV = (const float*)d_in[3];
    const float* W_UK  = (const float*)d_in[4];
    const float* W_UV  = (const float*)d_in[5];
    const float* W_QR  = (const float*)d_in[6];
    const float* W_KR  = (const float*)d_in[7];
    const float* W_O   = (const float*)d_in[8];
    float* out = (float*)d_out;

    float *cQ, *cKV, *qC, *kC, *v, *qR, *kR, *Q, *K, *V, *S, *Y;
    cudaGetSymbolAddress((void**)&cQ,  g_cQ);
    cudaGetSymbolAddress((void**)&cKV, g_cKV);
    cudaGetSymbolAddress((void**)&qC,  g_qC);
    cudaGetSymbolAddress((void**)&kC,  g_kC);
    cudaGetSymbolAddress((void**)&v,   g_v);
    cudaGetSymbolAddress((void**)&qR,  g_qR);
    cudaGetSymbolAddress((void**)&kR,  g_kR);
    cudaGetSymbolAddress((void**)&Q,   g_Q);
    cudaGetSymbolAddress((void**)&K,   g_K);
    cudaGetSymbolAddress((void**)&V,   g_V);
    cudaGetSymbolAddress((void**)&S,   g_S);
    cudaGetSymbolAddress((void**)&Y,   g_Y);

    // 1. cQ = x @ W_DQ              (8192, 4096, 1024)
    gemm_tc<128,128,32,64,32,false,false><<<dim3(4096/128, MM/128, 1), 256>>>(
        x, W_DQ, cQ, MM, 4096, 1024, 0, 0, 0, 0, 1, 4096);
    // 2. qC = cQ @ W_UQ             (8192, 1024, 4096)
    gemm_tc<128,128,32,64,32,false,false><<<dim3(1024/128, MM/128, 1), 256>>>(
        cQ, W_UQ, qC, MM, 1024, 4096, 0, 0, 0, 0, 1, 1024);
    // 3. cKV = x @ W_DKV            (8192, 256, 1024)
    gemm_tc<128,128,32,64,32,false,false><<<dim3(256/128, MM/128, 1), 256>>>(
        x, W_DKV, cKV, MM, 256, 1024, 0, 0, 0, 0, 1, 256);
    // 4. kC = cKV @ W_UK            (8192, 1024, 256)
    gemm_tc<128,128,32,64,32,false,false><<<dim3(1024/128, MM/128, 1), 256>>>(
        cKV, W_UK, kC, MM, 1024, 256, 0, 0, 0, 0, 1, 1024);
    // 5. v = cKV @ W_UV             (8192, 1024, 256)
    gemm_tc<128,128,32,64,32,false,false><<<dim3(1024/128, MM/128, 1), 256>>>(
        cKV, W_UV, v, MM, 1024, 256, 0, 0, 0, 0, 1, 1024);
    // 6. qR = cQ @ W_QR             (8192, 512, 4096)
    gemm_tc<128,128,32,64,32,false,false><<<dim3(512/128, MM/128, 1), 256>>>(
        cQ, W_QR, qR, MM, 512, 4096, 0, 0, 0, 0, 1, 512);
    // 7. kR = x @ W_KR              (8192, 32, 1024)
    gemm_n32<<<(MM*32)/256, 256>>>(x, W_KR, kR, MM, 1024);

    // 8. assemble Q/K/V with RoPE scale
    {
        long long total = (long long)BH * Tt * Dd;
        int blocks = (int)((total + 255) / 256);
        assemble_qkv<<<blocks, 256>>>(qC, qR, kC, kR, v, Q, K, V);
    }

    // 9. S = Q @ K^T  batched over 64 (b,h), causal tile skip  (2048,2048,96)
    gemm_tc<128,128,32,64,32,true,true><<<dim3(Tt/128, Tt/128, BH), 256>>>(
        Q, K, S, Tt, Tt, Dd,
        (long long)Tt*Dd, (long long)Tt*Dd,
        (long long)Tt*Tt, 0, 1, Tt);

    // 10. causal softmax over rows of S (truncated to valid prefix)
    softmax_causal<<<BH*Tt, 256>>>(S, 1.0f / sqrtf((float)Dd));

    // 11. Y = P @ V  batched, causal k-bound, writes (B,T,H*HS) layout
    gemm_tc<128,64,32,32,32,false,true><<<dim3(1, Tt/128, BH), 256>>>(
        S, V, Y, Tt, HS_, Tt,
        (long long)Tt*Tt, (long long)Tt*HS_,
        (long long)Tt*Cc_, (long long)HS_, Hh, Cc_);

    // 12. out = Y @ W_O             (8192, 1024, 1024)
    gemm_tc<128,128,32,64,32,false,false><<<dim3(1024/128, MM/128, 1), 256>>>(
        Y, W_O, out, MM, 1024, 1024, 0, 0, 0, 0, 1, 1024);
}

// round 6
// speedup vs baseline: 2.9188x; 1.4287x over previous
#include <cuda_runtime.h>
#include <cuda_bf16.h>
#include <math.h>
#include <stdint.h>

// ---------------------------------------------------------------------------
// MLA attention, TF32 tensor cores + cp.async 2-stage pipelined GEMM.
// B=4, T=2048, C=1024, H=16, HS=64, DHR=32, D=HS+DHR=96, M=B*T=8192
// All GEMM operands are pre-rounded to tf32 (rna) so cp.async can copy raw.
// ---------------------------------------------------------------------------

#define Bb   4
#define Tt   2048
#define Cc_  1024
#define Hh   16
#define HS_  64
#define DHR_ 32
#define Dd   96
#define MM   (Bb*Tt)          // 8192
#define BH   (Bb*Hh)          // 64

// ------------------------- scratch (static device) -------------------------
__device__ float g_cQ [(size_t)MM*4096];
__device__ float g_cKV[(size_t)MM*256];
__device__ float g_qC [(size_t)MM*1024];
__device__ float g_kC [(size_t)MM*1024];
__device__ float g_v  [(size_t)MM*1024];
__device__ float g_qR [(size_t)MM*512];
__device__ float g_kR [(size_t)MM*32];
__device__ float g_Q  [(size_t)BH*Tt*Dd];
__device__ float g_K  [(size_t)BH*Tt*Dd];
__device__ float g_V  [(size_t)BH*Tt*HS_];
__device__ float g_S  [(size_t)BH*Tt*Tt];
__device__ float g_Y  [(size_t)MM*1024];
// tf32-rounded copies of inputs
__device__ float g_x  [(size_t)MM*Cc_];
__device__ float g_wdq [(size_t)Cc_*4096];
__device__ float g_wuq [(size_t)4096*Cc_];
__device__ float g_wdkv[(size_t)Cc_*256];
__device__ float g_wuk [(size_t)256*Cc_];
__device__ float g_wuv [(size_t)256*Cc_];
__device__ float g_wqr [(size_t)4096*512];
__device__ float g_wkr [(size_t)Cc_*32];
__device__ float g_wo  [(size_t)Cc_*Cc_];

// ------------------------- helpers -----------------------------------------
__device__ __forceinline__ float to_tf32(float f) {
    uint32_t u;
    asm("cvt.rna.tf32.f32 %0, %1;" : "=r"(u) : "f"(f));
    return __uint_as_float(u);
}

__device__ __forceinline__ void mma_tf32(float* c, const uint32_t* a, const uint32_t* b) {
    asm volatile(
        "mma.sync.aligned.m16n8k8.row.col.f32.tf32.tf32.f32 "
        "{%0,%1,%2,%3}, {%4,%5,%6,%7}, {%8,%9}, {%0,%1,%2,%3};"
        : "+f"(c[0]), "+f"(c[1]), "+f"(c[2]), "+f"(c[3])
        : "r"(a[0]), "r"(a[1]), "r"(a[2]), "r"(a[3]),
          "r"(b[0]), "r"(b[1]));
}

__device__ __forceinline__ void cp16(uint32_t dst, const void* src) {
    asm volatile("cp.async.cg.shared.global [%0], [%1], 16;" :: "r"(dst), "l"(src));
}
__device__ __forceinline__ uint32_t smem_u32(const void* p) {
    return (uint32_t)__cvta_generic_to_shared(p);
}

// ------------------- TF32 pipelined tensor-core GEMM -----------------------
// C = A(MxK) * B(KxN)   (TRB=false)      A,B pre-rounded to tf32
// C = A(MxK) * B(NxK)^T (TRB=true)
// CAUSAL: TRB -> skip fully masked tiles; !TRB -> bound k-loop at bm+BM.
// ROUND:  round C to tf32 on store (when C feeds a later GEMM).
template<int BM,int BN,int BK,int WM,int WN,bool TRB,bool CAUSAL,bool ROUND>
__global__ void __launch_bounds__(256, 1)
gemm_tc(const float* __restrict__ A,
        const float* __restrict__ B,
        float* __restrict__ C,
        int M, int N, int K,
        long long sA, long long sB,
        long long cB, long long cH, int Hdiv, int ldc)
{
    constexpr int WARPS_N = BN/WN;
    constexpr int THREADS = 256;
    constexpr int MT = WM/16;
    constexpr int NT = WN/8;
    constexpr int ASTR  = BK+4;                 // padded row (floats)
    constexpr int BROWS = TRB ? BN : BK;
    constexpr int BSTR  = (TRB ? BK : BN) + 4;
    constexpr int ASZ = BM*ASTR;                // floats per stage
    constexpr int BSZ = BROWS*BSTR;

    const int bm = blockIdx.y * BM;
    const int bn = blockIdx.x * BN;
    if (CAUSAL && TRB && bn > bm + BM - 1) return;   // fully masked S tile

    extern __shared__ float smem[];
    float* As = smem;                  // [2][ASZ]
    float* Bs = smem + 2*ASZ;          // [2][BSZ]
    const uint32_t s_as = smem_u32(As);
    const uint32_t s_bs = smem_u32(Bs);

    const int z = blockIdx.z;
    A += (long long)z * sA;
    B += (long long)z * sB;
    C += (long long)(z / Hdiv) * cB + (long long)(z % Hdiv) * cH;

    const int tid  = threadIdx.x;
    const int warp = tid >> 5;
    const int lane = tid & 31;
    const int lr   = lane >> 2;   // 0..7
    const int lc   = lane & 3;    // 0..3
    const int wm0  = (warp / WARPS_N) * WM;
    const int wn0  = (warp % WARPS_N) * WN;

    float acc[MT][NT][4];
    #pragma unroll
    for (int i = 0; i < MT; i++)
        #pragma unroll
        for (int j = 0; j < NT; j++)
            #pragma unroll
            for (int r = 0; r < 4; r++) acc[i][j][r] = 0.f;

    const int kend   = (CAUSAL && !TRB) ? min(K, bm + BM) : K;
    const int ntiles = kend / BK;

    // ---- async tile loader: tile kt into stage buf ----
    auto load_tile = [&](int kt, int buf) {
        const int k0 = kt * BK;
        // A tile: BM rows x BK floats
        #pragma unroll
        for (int i = tid; i < BM*(BK/4); i += THREADS) {
            int m  = i / (BK/4);
            int kq = i % (BK/4);
            cp16(s_as + (uint32_t)(buf*ASZ + m*ASTR + kq*4)*4u,
                 A + (long long)(bm+m)*K + k0 + kq*4);
        }
        if (!TRB) {
            // B tile: BK rows x BN floats
            #pragma unroll
            for (int i = tid; i < BK*(BN/4); i += THREADS) {
                int kr = i / (BN/4);
                int nq = i % (BN/4);
                cp16(s_bs + (uint32_t)(buf*BSZ + kr*BSTR + nq*4)*4u,
                     B + (long long)(k0+kr)*N + bn + nq*4);
            }
        } else {
            // B tile: BN rows x BK floats
            #pragma unroll
            for (int i = tid; i < BN*(BK/4); i += THREADS) {
                int nr = i / (BK/4);
                int kq = i % (BK/4);
                cp16(s_bs + (uint32_t)(buf*BSZ + nr*BSTR + kq*4)*4u,
                     B + (long long)(bn+nr)*K + k0 + kq*4);
            }
        }
    };

    load_tile(0, 0);
    asm volatile("cp.async.commit_group;");

    for (int kt = 0; kt < ntiles; kt++) {
        const int buf = kt & 1;
        if (kt + 1 < ntiles) {
            load_tile(kt+1, buf^1);
            asm volatile("cp.async.commit_group;");
            asm volatile("cp.async.wait_group 1;");
        } else {
            asm volatile("cp.async.wait_group 0;");
        }
        __syncthreads();

        const float* Atile = As + buf*ASZ;
        const float* Btile = Bs + buf*BSZ;

        #pragma unroll
        for (int kk = 0; kk < BK; kk += 8) {
            uint32_t a[MT][4], b[NT][2];
            #pragma unroll
            for (int mt = 0; mt < MT; mt++) {
                const float* ap = Atile + (wm0 + mt*16 + lr)*ASTR + kk + lc;
                a[mt][0] = __float_as_uint(ap[0]);
                a[mt][1] = __float_as_uint(ap[8*ASTR]);
                a[mt][2] = __float_as_uint(ap[4]);
                a[mt][3] = __float_as_uint(ap[8*ASTR + 4]);
            }
            #pragma unroll
            for (int nt = 0; nt < NT; nt++) {
                if (!TRB) {
                    const float* bp = Btile + (kk+lc)*BSTR + wn0 + nt*8 + lr;
                    b[nt][0] = __float_as_uint(bp[0]);
                    b[nt][1] = __float_as_uint(bp[4*BSTR]);
                } else {
                    const float* bp = Btile + (wn0 + nt*8 + lr)*BSTR + kk + lc;
                    b[nt][0] = __float_as_uint(bp[0]);
                    b[nt][1] = __float_as_uint(bp[4]);
                }
            }
            #pragma unroll
            for (int mt = 0; mt < MT; mt++)
                #pragma unroll
                for (int nt = 0; nt < NT; nt++)
                    mma_tf32(acc[mt][nt], a[mt], b[nt]);
        }
        __syncthreads();
    }

    // --- store ---
    #pragma unroll
    for (int mt = 0; mt < MT; mt++) {
        int row0 = bm + wm0 + mt*16 + lr;
        #pragma unroll
        for (int nt = 0; nt < NT; nt++) {
            int col = bn + wn0 + nt*8 + 2*lc;
            float2 v0, v1;
            if (ROUND) {
                v0 = make_float2(to_tf32(acc[mt][nt][0]), to_tf32(acc[mt][nt][1]));
                v1 = make_float2(to_tf32(acc[mt][nt][2]), to_tf32(acc[mt][nt][3]));
            } else {
                v0 = make_float2(acc[mt][nt][0], acc[mt][nt][1]);
                v1 = make_float2(acc[mt][nt][2], acc[mt][nt][3]);
            }
            *(float2*)(C + (long long)row0*ldc + col)     = v0;
            *(float2*)(C + (long long)(row0+8)*ldc + col) = v1;
        }
    }
}

// ------------------------- tf32 round-copy ---------------------------------
__global__ void round_copy(const float* __restrict__ src, float* __restrict__ dst, int n)
{
    for (int i = blockIdx.x*blockDim.x + threadIdx.x; i < n;
         i += gridDim.x*blockDim.x)
        dst[i] = to_tf32(src[i]);
}

// ------------------------- small-N GEMM (k_R, N=32) ------------------------
__global__ void gemm_n32(const float* __restrict__ A, const float* __restrict__ Bw,
                         float* __restrict__ Cm, int M, int K)
{
    int gw   = (blockIdx.x * blockDim.x + threadIdx.x) >> 5;
    int lane = threadIdx.x & 31;
    if (gw >= M) return;
    const float* a = A + (long long)gw * K;
    float acc = 0.f;
    #pragma unroll 8
    for (int k = 0; k < K; k++)
        acc += a[k] * Bw[k*32 + lane];
    Cm[(long long)gw*32 + lane] = acc;
}

// --------------------- assemble Q/K/V with RoPE scale ----------------------
__constant__ float c_inv[16] = {
    1.0f, 0.5623413251903491f, 0.31622776601683794f, 0.17782794100389228f,
    0.1f, 0.05623413251903491f, 0.031622776601683794f, 0.017782794100389228f,
    0.01f, 0.005623413251903491f, 0.0031622776601683794f, 0.0017782794100389228f,
    0.001f, 0.0005623413251903491f, 0.00031622776601683794f, 0.00017782794100389228f
};

__global__ void assemble_qkv(const float* __restrict__ qC, const float* __restrict__ qR,
                             const float* __restrict__ kC, const float* __restrict__ kR,
                             const float* __restrict__ vr,
                             float* __restrict__ Q, float* __restrict__ K,
                             float* __restrict__ V)
{
    const long long total = (long long)BH * Tt * Dd;
    for (long long idx = (long long)blockIdx.x * blockDim.x + threadIdx.x;
         idx < total; idx += (long long)gridDim.x * blockDim.x)
    {
        int d = (int)(idx % Dd);
        long long r = idx / Dd;            // (b,h,t)
        int t = (int)(r % Tt);
        long long r2 = r / Tt;             // (b,h)
        int h = (int)(r2 % Hh);
        int b = (int)(r2 / Hh);
        long long bt = (long long)b * Tt + t;

        float qv, kv;
        if (d < HS_) {
            long long src = bt * 1024 + h * HS_ + d;
            qv = qC[src];
            kv = kC[src];
            V[(r2 * Tt + t) * HS_ + d] = to_tf32(vr[src]);
        } else {
            int j  = d - HS_;
            int fi = j & 15;
            float ang = (float)t * c_inv[fi];
            float s_, co;
            sincosf(ang, &s_, &co);
            float sc = co + s_;
            qv = qR[bt * 512 + h * DHR_ + j] * sc;
            kv = kR[bt * 32 + j] * sc;
        }
        Q[idx] = to_tf32(qv);
        K[idx] = to_tf32(kv);
    }
}

// ------------------- causal softmax (rows of S, truncated) -----------------
__global__ void softmax_causal(float* __restrict__ S, float scale)
{
    long long r = blockIdx.x;              // (b*H+h)*T + q
    int q = (int)(r % Tt);
    int qb_end = ((q >> 7) + 1) << 7;      // multiple of 128
    float* row = S + r * Tt;
    int tid = threadIdx.x;

    float vals[8];
    #pragma unroll
    for (int i = 0; i < 8; i++) vals[i] = -1e30f;

    float mx = -1e30f;
    for (int i = 0; i*256 < qb_end; i++) {
        int c = tid + i*256;
        if (c < qb_end) {
            float v = (c <= q) ? row[c]*scale : -1e30f;
            vals[i] = v;
            mx = fmaxf(mx, v);
        }
    }

    __shared__ float red[8];
    #pragma unroll
    for (int o = 16; o > 0; o >>= 1) mx = fmaxf(mx, __shfl_xor_sync(0xffffffffu, mx, o));
    if ((tid & 31) == 0) red[tid >> 5] = mx;
    __syncthreads();
    if (tid < 32) {
        float v = (tid < 8) ? red[tid] : -1e30f;
        #pragma unroll
        for (int o = 4; o > 0; o >>= 1) v = fmaxf(v, __shfl_xor_sync(0xffffffffu, v, o));
        if (tid == 0) red[0] = v;
    }
    __syncthreads();
    mx = red[0];
    __syncthreads();

    float s = 0.f;
    for (int i = 0; i*256 < qb_end; i++) {
        int c = tid + i*256;
        if (c < qb_end) {
            float p = (vals[i] > -1e29f) ? expf(vals[i] - mx) : 0.f;
            vals[i] = p;
            s += p;
        }
    }
    #pragma unroll
    for (int o = 16; o > 0; o >>= 1) s += __shfl_xor_sync(0xffffffffu, s, o);
    if ((tid & 31) == 0) red[tid >> 5] = s;
    __syncthreads();
    if (tid < 32) {
        float v = (tid < 8) ? red[tid] : 0.f;
        #pragma unroll
        for (int o = 4; o > 0; o >>= 1) v += __shfl_xor_sync(0xffffffffu, v, o);
        if (tid == 0) red[0] = v;
    }
    __syncthreads();
    float invs = 1.f / red[0];

    for (int i = 0; i*256 < qb_end; i++) {
        int c = tid + i*256;
        if (c < qb_end)
            row[c] = (c <= q) ? to_tf32(vals[i] * invs) : 0.f;
    }
}

// ---------------------------------------------------------------------------
extern "C" void kernel_launch(void* const* d_in, const int* in_sizes, int n_in,
                              void* d_out, int out_size)
{
    const float* x     = (const float*)d_in[0];
    const float* W_DQ  = (const float*)d_in[1];
    const float* W_UQ  = (const float*)d_in[2];
    const float* W_DKV = (const float*)d_in[3];
    const float* W_UK  = (const float*)d_in[4];
    const float* W_UV  = (const float*)d_in[5];
    const float* W_QR  = (const float*)d_in[6];
    const float* W_KR  = (const float*)d_in[7];
    const float* W_O   = (const float*)d_in[8];
    float* out = (float*)d_out;

    float *cQ,*cKV,*qC,*kC,*v,*qR,*kR,*Q,*K,*V,*S,*Y;
    float *xr,*wdq,*wuq,*wdkv,*wuk,*wuv,*wqr,*wkr,*wo;
    cudaGetSymbolAddress((void**)&cQ,  g_cQ);
    cudaGetSymbolAddress((void**)&cKV, g_cKV);
    cudaGetSymbolAddress((void**)&qC,  g_qC);
    cudaGetSymbolAddress((void**)&kC,  g_kC);
    cudaGetSymbolAddress((void**)&v,   g_v);
    cudaGetSymbolAddress((void**)&qR,  g_qR);
    cudaGetSymbolAddress((void**)&kR,  g_kR);
    cudaGetSymbolAddress((void**)&Q,   g_Q);
    cudaGetSymbolAddress((void**)&K,   g_K);
    cudaGetSymbolAddress((void**)&V,   g_V);
    cudaGetSymbolAddress((void**)&S,   g_S);
    cudaGetSymbolAddress((void**)&Y,   g_Y);
    cudaGetSymbolAddress((void**)&xr,  g_x);
    cudaGetSymbolAddress((void**)&wdq, g_wdq);
    cudaGetSymbolAddress((void**)&wuq, g_wuq);
    cudaGetSymbolAddress((void**)&wdkv,g_wdkv);
    cudaGetSymbolAddress((void**)&wuk, g_wuk);
    cudaGetSymbolAddress((void**)&wuv, g_wuv);
    cudaGetSymbolAddress((void**)&wqr, g_wqr);
    cudaGetSymbolAddress((void**)&wkr, g_wkr);
    cudaGetSymbolAddress((void**)&wo,  g_wo);

    // smem sizes (bytes) per GEMM config
    const int SM_MAIN = (2*128*(32+4) + 2*32*(128+4)) * 4;   // !TRB 128x128
    const int SM_QK   = (2*128*(32+4) + 2*128*(32+4)) * 4;   // TRB 128x128
    const int SM_PV   = (2*128*(32+4) + 2*32*(64+4))  * 4;   // !TRB 128x64

    #define GEMM_MAIN gemm_tc<128,128,32,64,32,false,false,true>
    #define GEMM_OUT  gemm_tc<128,128,32,64,32,false,false,false>
    #define GEMM_QK   gemm_tc<128,128,32,64,32,true ,true ,false>
    #define GEMM_PV   gemm_tc<128,64 ,32,32,32,false,true ,true >

    cudaFuncSetAttribute(GEMM_MAIN, cudaFuncAttributeMaxDynamicSharedMemorySize, SM_MAIN);
    cudaFuncSetAttribute(GEMM_OUT,  cudaFuncAttributeMaxDynamicSharedMemorySize, SM_MAIN);
    cudaFuncSetAttribute(GEMM_QK,   cudaFuncAttributeMaxDynamicSharedMemorySize, SM_QK);
    cudaFuncSetAttribute(GEMM_PV,   cudaFuncAttributeMaxDynamicSharedMemorySize, SM_PV);

    // 0. pre-round inputs to tf32
    round_copy<<<1024,256>>>(x,     xr,   MM*Cc_);
    round_copy<<<1024,256>>>(W_DQ,  wdq,  Cc_*4096);
    round_copy<<<1024,256>>>(W_UQ,  wuq,  4096*Cc_);
    round_copy<<<256, 256>>>(W_DKV, wdkv, Cc_*256);
    round_copy<<<256, 256>>>(W_UK,  wuk,  256*Cc_);
    round_copy<<<256, 256>>>(W_UV,  wuv,  256*Cc_);
    round_copy<<<1024,256>>>(W_QR,  wqr,  4096*512);
    round_copy<<<64,  256>>>(W_KR,  wkr,  Cc_*32);
    round_copy<<<512, 256>>>(W_O,   wo,   Cc_*Cc_);

    // 1. cQ = x @ W_DQ              (8192, 4096, 1024)
    GEMM_MAIN<<<dim3(4096/128, MM/128, 1), 256, SM_MAIN>>>(
        xr, wdq, cQ, MM, 4096, 1024, 0, 0, 0, 0, 1, 4096);
    // 2. qC = cQ @ W_UQ             (8192, 1024, 4096)
    GEMM_OUT<<<dim3(1024/128, MM/128, 1), 256, SM_MAIN>>>(
        cQ, wuq, qC, MM, 1024, 4096, 0, 0, 0, 0, 1, 1024);
    // 3. cKV = x @ W_DKV            (8192, 256, 1024)
    GEMM_MAIN<<<dim3(256/128, MM/128, 1), 256, SM_MAIN>>>(
        xr, wdkv, cKV, MM, 256, 1024, 0, 0, 0, 0, 1, 256);
    // 4. kC = cKV @ W_UK            (8192, 1024, 256)
    GEMM_OUT<<<dim3(1024/128, MM/128, 1), 256, SM_MAIN>>>(
        cKV, wuk, kC, MM, 1024, 256, 0, 0, 0, 0, 1, 1024);
    // 5. v = cKV @ W_UV             (8192, 1024, 256)
    GEMM_OUT<<<dim3(1024/128, MM/128, 1), 256, SM_MAIN>>>(
        cKV, wuv, v, MM, 1024, 256, 0, 0, 0, 0, 1, 1024);
    // 6. qR = cQ @ W_QR             (8192, 512, 4096)
    GEMM_OUT<<<dim3(512/128, MM/128, 1), 256, SM_MAIN>>>(
        cQ, wqr, qR, MM, 512, 4096, 0, 0, 0, 0, 1, 512);
    // 7. kR = x @ W_KR              (8192, 32, 1024)
    gemm_n32<<<(MM*32)/256, 256>>>(xr, wkr, kR, MM, 1024);

    // 8. assemble Q/K/V with RoPE scale (rounds outputs to tf32)
    {
        long long total = (long long)BH * Tt * Dd;
        int blocks = (int)((total + 255) / 256);
        assemble_qkv<<<blocks, 256>>>(qC, qR, kC, kR, v, Q, K, V);
    }

    // 9. S = Q @ K^T  batched over 64 (b,h), causal tile skip  (2048,2048,96)
    GEMM_QK<<<dim3(Tt/128, Tt/128, BH), 256, SM_QK>>>(
        Q, K, S, Tt, Tt, Dd,
        (long long)Tt*Dd, (long long)Tt*Dd,
        (long long)Tt*Tt, 0, 1, Tt);

    // 10. causal softmax over rows of S (rounds P to tf32)
    softmax_causal<<<BH*Tt, 256>>>(S, 1.0f / sqrtf((float)Dd));

    // 11. Y = P @ V  batched, causal k-bound, writes (B,T,H*HS) layout
    GEMM_PV<<<dim3(1, Tt/128, BH), 256, SM_PV>>>(
        S, V, Y, Tt, HS_, Tt,
        (long long)Tt*Tt, (long long)Tt*HS_,
        (long long)Tt*Cc_, (long long)HS_, Hh, Cc_);

    // 12. out = Y @ W_O             (8192, 1024, 1024)
    GEMM_OUT<<<dim3(1024/128, MM/128, 1), 256, SM_MAIN>>>(
        Y, wo, out, MM, 1024, 1024, 0, 0, 0, 0, 1, 1024);
}

// round 8
// speedup vs baseline: 3.5253x; 1.2078x over previous
#include <cuda_runtime.h>
#include <cuda_bf16.h>
#include <math.h>
#include <stdint.h>

// ---------------------------------------------------------------------------
// MLA attention, TF32 tensor cores + cp.async 2-stage pipelined GEMM.
// R7: 2 CTAs/SM (__launch_bounds__(256,2)) + fused {qC|qR} and {kC|v} GEMMs.
// B=4, T=2048, C=1024, H=16, HS=64, DHR=32, D=HS+DHR=96, M=B*T=8192
// ---------------------------------------------------------------------------

#define Bb   4
#define Tt   2048
#define Cc_  1024
#define Hh   16
#define HS_  64
#define DHR_ 32
#define Dd   96
#define MM   (Bb*Tt)          // 8192
#define BH   (Bb*Hh)          // 64

// ------------------------- scratch (static device) -------------------------
__device__ float g_cQ  [(size_t)MM*4096];
__device__ float g_cKV [(size_t)MM*256];
__device__ float g_qCR [(size_t)MM*1536];   // qC (0..1023) | qR (1024..1535)
__device__ float g_kCv [(size_t)MM*2048];   // kC (0..1023) | v  (1024..2047)
__device__ float g_kR  [(size_t)MM*32];
__device__ float g_Q   [(size_t)BH*Tt*Dd];
__device__ float g_K   [(size_t)BH*Tt*Dd];
__device__ float g_V   [(size_t)BH*Tt*HS_];
__device__ float g_S   [(size_t)BH*Tt*Tt];
__device__ float g_Y   [(size_t)MM*1024];
// tf32-rounded copies of inputs
__device__ float g_x    [(size_t)MM*Cc_];
__device__ float g_wdq  [(size_t)Cc_*4096];
__device__ float g_wuqr [(size_t)4096*1536];   // W_UQ | W_QR
__device__ float g_wdkv [(size_t)Cc_*256];
__device__ float g_wukv [(size_t)256*2048];    // W_UK | W_UV
__device__ float g_wkr  [(size_t)Cc_*32];
__device__ float g_wo   [(size_t)Cc_*Cc_];

// ------------------------- helpers -----------------------------------------
__device__ __forceinline__ float to_tf32(float f) {
    uint32_t u;
    asm("cvt.rna.tf32.f32 %0, %1;" : "=r"(u) : "f"(f));
    return __uint_as_float(u);
}

__device__ __forceinline__ void mma_tf32(float* c, const uint32_t* a, const uint32_t* b) {
    asm volatile(
        "mma.sync.aligned.m16n8k8.row.col.f32.tf32.tf32.f32 "
        "{%0,%1,%2,%3}, {%4,%5,%6,%7}, {%8,%9}, {%0,%1,%2,%3};"
        : "+f"(c[0]), "+f"(c[1]), "+f"(c[2]), "+f"(c[3])
        : "r"(a[0]), "r"(a[1]), "r"(a[2]), "r"(a[3]),
          "r"(b[0]), "r"(b[1]));
}

__device__ __forceinline__ void cp16(uint32_t dst, const void* src) {
    asm volatile("cp.async.cg.shared.global [%0], [%1], 16;" :: "r"(dst), "l"(src));
}
__device__ __forceinline__ uint32_t smem_u32(const void* p) {
    return (uint32_t)__cvta_generic_to_shared(p);
}

// ------------------- TF32 pipelined tensor-core GEMM -----------------------
// C = A(MxK) * B(KxN)   (TRB=false)      A,B pre-rounded to tf32
// C = A(MxK) * B(NxK)^T (TRB=true)
// CAUSAL: TRB -> skip fully masked tiles; !TRB -> bound k-loop at bm+BM.
// ROUND:  round C to tf32 on store (when C feeds a later GEMM).
template<int BM,int BN,int BK,int WM,int WN,bool TRB,bool CAUSAL,bool ROUND>
__global__ void __launch_bounds__(256, 2)
gemm_tc(const float* __restrict__ A,
        const float* __restrict__ B,
        float* __restrict__ C,
        int M, int N, int K,
        long long sA, long long sB,
        long long cB, long long cH, int Hdiv, int ldc)
{
    constexpr int WARPS_N = BN/WN;
    constexpr int THREADS = 256;
    constexpr int MT = WM/16;
    constexpr int NT = WN/8;
    constexpr int ASTR  = BK+4;                 // padded row (floats)
    constexpr int BROWS = TRB ? BN : BK;
    constexpr int BSTR  = (TRB ? BK : BN) + 4;
    constexpr int ASZ = BM*ASTR;                // floats per stage
    constexpr int BSZ = BROWS*BSTR;

    const int bm = blockIdx.y * BM;
    const int bn = blockIdx.x * BN;
    if (CAUSAL && TRB && bn > bm + BM - 1) return;   // fully masked S tile

    extern __shared__ float smem[];
    float* As = smem;                  // [2][ASZ]
    float* Bs = smem + 2*ASZ;          // [2][BSZ]
    const uint32_t s_as = smem_u32(As);
    const uint32_t s_bs = smem_u32(Bs);

    const int z = blockIdx.z;
    A += (long long)z * sA;
    B += (long long)z * sB;
    C += (long long)(z / Hdiv) * cB + (long long)(z % Hdiv) * cH;

    const int tid  = threadIdx.x;
    const int warp = tid >> 5;
    const int lane = tid & 31;
    const int lr   = lane >> 2;   // 0..7
    const int lc   = lane & 3;    // 0..3
    const int wm0  = (warp / WARPS_N) * WM;
    const int wn0  = (warp % WARPS_N) * WN;

    float acc[MT][NT][4];
    #pragma unroll
    for (int i = 0; i < MT; i++)
        #pragma unroll
        for (int j = 0; j < NT; j++)
            #pragma unroll
            for (int r = 0; r < 4; r++) acc[i][j][r] = 0.f;

    const int kend   = (CAUSAL && !TRB) ? min(K, bm + BM) : K;
    const int ntiles = kend / BK;

    // ---- async tile loader: tile kt into stage buf ----
    auto load_tile = [&](int kt, int buf) {
        const int k0 = kt * BK;
        // A tile: BM rows x BK floats
        #pragma unroll
        for (int i = tid; i < BM*(BK/4); i += THREADS) {
            int m  = i / (BK/4);
            int kq = i % (BK/4);
            cp16(s_as + (uint32_t)(buf*ASZ + m*ASTR + kq*4)*4u,
                 A + (long long)(bm+m)*K + k0 + kq*4);
        }
        if (!TRB) {
            // B tile: BK rows x BN floats
            #pragma unroll
            for (int i = tid; i < BK*(BN/4); i += THREADS) {
                int kr = i / (BN/4);
                int nq = i % (BN/4);
                cp16(s_bs + (uint32_t)(buf*BSZ + kr*BSTR + nq*4)*4u,
                     B + (long long)(k0+kr)*N + bn + nq*4);
            }
        } else {
            // B tile: BN rows x BK floats
            #pragma unroll
            for (int i = tid; i < BN*(BK/4); i += THREADS) {
                int nr = i / (BK/4);
                int kq = i % (BK/4);
                cp16(s_bs + (uint32_t)(buf*BSZ + nr*BSTR + kq*4)*4u,
                     B + (long long)(bn+nr)*K + k0 + kq*4);
            }
        }
    };

    load_tile(0, 0);
    asm volatile("cp.async.commit_group;");

    for (int kt = 0; kt < ntiles; kt++) {
        const int buf = kt & 1;
        if (kt + 1 < ntiles) {
            load_tile(kt+1, buf^1);
            asm volatile("cp.async.commit_group;");
            asm volatile("cp.async.wait_group 1;");
        } else {
            asm volatile("cp.async.wait_group 0;");
        }
        __syncthreads();

        const float* Atile = As + buf*ASZ;
        const float* Btile = Bs + buf*BSZ;

        #pragma unroll
        for (int kk = 0; kk < BK; kk += 8) {
            uint32_t a[MT][4], b[NT][2];
            #pragma unroll
            for (int mt = 0; mt < MT; mt++) {
                const float* ap = Atile + (wm0 + mt*16 + lr)*ASTR + kk + lc;
                a[mt][0] = __float_as_uint(ap[0]);
                a[mt][1] = __float_as_uint(ap[8*ASTR]);
                a[mt][2] = __float_as_uint(ap[4]);
                a[mt][3] = __float_as_uint(ap[8*ASTR + 4]);
            }
            #pragma unroll
            for (int nt = 0; nt < NT; nt++) {
                if (!TRB) {
                    const float* bp = Btile + (kk+lc)*BSTR + wn0 + nt*8 + lr;
                    b[nt][0] = __float_as_uint(bp[0]);
                    b[nt][1] = __float_as_uint(bp[4*BSTR]);
                } else {
                    const float* bp = Btile + (wn0 + nt*8 + lr)*BSTR + kk + lc;
                    b[nt][0] = __float_as_uint(bp[0]);
                    b[nt][1] = __float_as_uint(bp[4]);
                }
            }
            #pragma unroll
            for (int mt = 0; mt < MT; mt++)
                #pragma unroll
                for (int nt = 0; nt < NT; nt++)
                    mma_tf32(acc[mt][nt], a[mt], b[nt]);
        }
        __syncthreads();
    }

    // --- store ---
    #pragma unroll
    for (int mt = 0; mt < MT; mt++) {
        int row0 = bm + wm0 + mt*16 + lr;
        #pragma unroll
        for (int nt = 0; nt < NT; nt++) {
            int col = bn + wn0 + nt*8 + 2*lc;
            float2 v0, v1;
            if (ROUND) {
                v0 = make_float2(to_tf32(acc[mt][nt][0]), to_tf32(acc[mt][nt][1]));
                v1 = make_float2(to_tf32(acc[mt][nt][2]), to_tf32(acc[mt][nt][3]));
            } else {
                v0 = make_float2(acc[mt][nt][0], acc[mt][nt][1]);
                v1 = make_float2(acc[mt][nt][2], acc[mt][nt][3]);
            }
            *(float2*)(C + (long long)row0*ldc + col)     = v0;
            *(float2*)(C + (long long)(row0+8)*ldc + col) = v1;
        }
    }
}

// ------------------------- tf32 round-copy ---------------------------------
__global__ void round_copy(const float* __restrict__ src, float* __restrict__ dst, int n)
{
    for (int i = blockIdx.x*blockDim.x + threadIdx.x; i < n;
         i += gridDim.x*blockDim.x)
        dst[i] = to_tf32(src[i]);
}

// strided: pack src (rows x cols, row-major) into dst rows of width ld at col off
__global__ void round_copy_off(const float* __restrict__ src, float* __restrict__ dst,
                               int rows, int cols, int ld, int off)
{
    long long n = (long long)rows*cols;
    for (long long i = (long long)blockIdx.x*blockDim.x + threadIdx.x; i < n;
         i += (long long)gridDim.x*blockDim.x) {
        int r = (int)(i / cols);
        int c = (int)(i % cols);
        dst[(long long)r*ld + off + c] = to_tf32(src[i]);
    }
}

// ------------------------- small-N GEMM (k_R, N=32) ------------------------
__global__ void gemm_n32(const float* __restrict__ A, const float* __restrict__ Bw,
                         float* __restrict__ Cm, int M, int K)
{
    int gw   = (blockIdx.x * blockDim.x + threadIdx.x) >> 5;
    int lane = threadIdx.x & 31;
    if (gw >= M) return;
    const float* a = A + (long long)gw * K;
    float acc = 0.f;
    #pragma unroll 8
    for (int k = 0; k < K; k++)
        acc += a[k] * Bw[k*32 + lane];
    Cm[(long long)gw*32 + lane] = acc;
}

// --------------------- assemble Q/K/V with RoPE scale ----------------------
__constant__ float c_inv[16] = {
    1.0f, 0.5623413251903491f, 0.31622776601683794f, 0.17782794100389228f,
    0.1f, 0.05623413251903491f, 0.031622776601683794f, 0.017782794100389228f,
    0.01f, 0.005623413251903491f, 0.0031622776601683794f, 0.0017782794100389228f,
    0.001f, 0.0005623413251903491f, 0.00031622776601683794f, 0.00017782794100389228f
};

// qCR: [M][1536] = qC | qR      kCv: [M][2048] = kC | v
__global__ void assemble_qkv(const float* __restrict__ qCR,
                             const float* __restrict__ kCv,
                             const float* __restrict__ kR,
                             float* __restrict__ Q, float* __restrict__ K,
                             float* __restrict__ V)
{
    const long long total = (long long)BH * Tt * Dd;
    for (long long idx = (long long)blockIdx.x * blockDim.x + threadIdx.x;
         idx < total; idx += (long long)gridDim.x * blockDim.x)
    {
        int d = (int)(idx % Dd);
        long long r = idx / Dd;            // (b,h,t)
        int t = (int)(r % Tt);
        long long r2 = r / Tt;             // (b,h)
        int h = (int)(r2 % Hh);
        int b = (int)(r2 / Hh);
        long long bt = (long long)b * Tt + t;

        float qv, kv;
        if (d < HS_) {
            qv = qCR[bt * 1536 + h * HS_ + d];
            kv = kCv[bt * 2048 + h * HS_ + d];
            V[(r2 * Tt + t) * HS_ + d] = to_tf32(kCv[bt * 2048 + 1024 + h * HS_ + d]);
        } else {
            int j  = d - HS_;
            int fi = j & 15;
            float ang = (float)t * c_inv[fi];
            float s_, co;
            sincosf(ang, &s_, &co);
            float sc = co + s_;
            qv = qCR[bt * 1536 + 1024 + h * DHR_ + j] * sc;
            kv = kR[bt * 32 + j] * sc;
        }
        Q[idx] = to_tf32(qv);
        K[idx] = to_tf32(kv);
    }
}

// ------------------- causal softmax (rows of S, truncated) -----------------
__global__ void softmax_causal(float* __restrict__ S, float scale)
{
    long long r = blockIdx.x;              // (b*H+h)*T + q
    int q = (int)(r % Tt);
    int qb_end = ((q >> 7) + 1) << 7;      // multiple of 128
    float* row = S + r * Tt;
    int tid = threadIdx.x;

    float vals[8];
    #pragma unroll
    for (int i = 0; i < 8; i++) vals[i] = -1e30f;

    float mx = -1e30f;
    for (int i = 0; i*256 < qb_end; i++) {
        int c = tid + i*256;
        if (c < qb_end) {
            float v = (c <= q) ? row[c]*scale : -1e30f;
            vals[i] = v;
            mx = fmaxf(mx, v);
        }
    }

    __shared__ float red[8];
    #pragma unroll
    for (int o = 16; o > 0; o >>= 1) mx = fmaxf(mx, __shfl_xor_sync(0xffffffffu, mx, o));
    if ((tid & 31) == 0) red[tid >> 5] = mx;
    __syncthreads();
    if (tid < 32) {
        float v = (tid < 8) ? red[tid] : -1e30f;
        #pragma unroll
        for (int o = 4; o > 0; o >>= 1) v = fmaxf(v, __shfl_xor_sync(0xffffffffu, v, o));
        if (tid == 0) red[0] = v;
    }
    __syncthreads();
    mx = red[0];
    __syncthreads();

    float s = 0.f;
    for (int i = 0; i*256 < qb_end; i++) {
        int c = tid + i*256;
        if (c < qb_end) {
            float p = (vals[i] > -1e29f) ? expf(vals[i] - mx) : 0.f;
            vals[i] = p;
            s += p;
        }
    }
    #pragma unroll
    for (int o = 16; o > 0; o >>= 1) s += __shfl_xor_sync(0xffffffffu, s, o);
    if ((tid & 31) == 0) red[tid >> 5] = s;
    __syncthreads();
    if (tid < 32) {
        float v = (tid < 8) ? red[tid] : 0.f;
        #pragma unroll
        for (int o = 4; o > 0; o >>= 1) v += __shfl_xor_sync(0xffffffffu, v, o);
        if (tid == 0) red[0] = v;
    }
    __syncthreads();
    float invs = 1.f / red[0];

    for (int i = 0; i*256 < qb_end; i++) {
        int c = tid + i*256;
        if (c < qb_end)
            row[c] = (c <= q) ? to_tf32(vals[i] * invs) : 0.f;
    }
}

// ---------------------------------------------------------------------------
extern "C" void kernel_launch(void* const* d_in, const int* in_sizes, int n_in,
                              void* d_out, int out_size)
{
    const float* x     = (const float*)d_in[0];
    const float* W_DQ  = (const float*)d_in[1];
    const float* W_UQ  = (const float*)d_in[2];
    const float* W_DKV = (const float*)d_in[3];
    const float* W_UK  = (const float*)d_in[4];
    const float* W_UV  = (const float*)d_in[5];
    const float* W_QR  = (const float*)d_in[6];
    const float* W_KR  = (const float*)d_in[7];
    const float* W_O   = (const float*)d_in[8];
    float* out = (float*)d_out;

    float *cQ,*cKV,*qCR,*kCv,*kR,*Q,*K,*V,*S,*Y;
    float *xr,*wdq,*wuqr,*wdkv,*wukv,*wkr,*wo;
    cudaGetSymbolAddress((void**)&cQ,  g_cQ);
    cudaGetSymbolAddress((void**)&cKV, g_cKV);
    cudaGetSymbolAddress((void**)&qCR, g_qCR);
    cudaGetSymbolAddress((void**)&kCv, g_kCv);
    cudaGetSymbolAddress((void**)&kR,  g_kR);
    cudaGetSymbolAddress((void**)&Q,   g_Q);
    cudaGetSymbolAddress((void**)&K,   g_K);
    cudaGetSymbolAddress((void**)&V,   g_V);
    cudaGetSymbolAddress((void**)&S,   g_S);
    cudaGetSymbolAddress((void**)&Y,   g_Y);
    cudaGetSymbolAddress((void**)&xr,  g_x);
    cudaGetSymbolAddress((void**)&wdq, g_wdq);
    cudaGetSymbolAddress((void**)&wuqr,g_wuqr);
    cudaGetSymbolAddress((void**)&wdkv,g_wdkv);
    cudaGetSymbolAddress((void**)&wukv,g_wukv);
    cudaGetSymbolAddress((void**)&wkr, g_wkr);
    cudaGetSymbolAddress((void**)&wo,  g_wo);

    // smem sizes (bytes) per GEMM config
    const int SM_MAIN = (2*128*(32+4) + 2*32*(128+4)) * 4;   // !TRB 128x128
    const int SM_QK   = (2*128*(32+4) + 2*128*(32+4)) * 4;   // TRB 128x128
    const int SM_PV   = (2*128*(32+4) + 2*32*(64+4))  * 4;   // !TRB 128x64

    #define GEMM_MAIN gemm_tc<128,128,32,64,32,false,false,true>
    #define GEMM_OUT  gemm_tc<128,128,32,64,32,false,false,false>
    #define GEMM_QK   gemm_tc<128,128,32,64,32,true ,true ,false>
    #define GEMM_PV   gemm_tc<128,64 ,32,32,32,false,true ,true >

    cudaFuncSetAttribute(GEMM_MAIN, cudaFuncAttributeMaxDynamicSharedMemorySize, SM_MAIN);
    cudaFuncSetAttribute(GEMM_OUT,  cudaFuncAttributeMaxDynamicSharedMemorySize, SM_MAIN);
    cudaFuncSetAttribute(GEMM_QK,   cudaFuncAttributeMaxDynamicSharedMemorySize, SM_QK);
    cudaFuncSetAttribute(GEMM_PV,   cudaFuncAttributeMaxDynamicSharedMemorySize, SM_PV);

    // 0. pre-round inputs to tf32 (with weight concat packing)
    round_copy<<<1024,256>>>(x,     xr,   MM*Cc_);
    round_copy<<<1024,256>>>(W_DQ,  wdq,  Cc_*4096);
    round_copy_off<<<1024,256>>>(W_UQ, wuqr, 4096, 1024, 1536, 0);
    round_copy_off<<<512, 256>>>(W_QR, wuqr, 4096, 512,  1536, 1024);
    round_copy<<<256, 256>>>(W_DKV, wdkv, Cc_*256);
    round_copy_off<<<256, 256>>>(W_UK, wukv, 256, 1024, 2048, 0);
    round_copy_off<<<256, 256>>>(W_UV, wukv, 256, 1024, 2048, 1024);
    round_copy<<<64,  256>>>(W_KR,  wkr,  Cc_*32);
    round_copy<<<512, 256>>>(W_O,   wo,   Cc_*Cc_);

    // 1. cQ = x @ W_DQ              (8192, 4096, 1024)
    GEMM_MAIN<<<dim3(4096/128, MM/128, 1), 256, SM_MAIN>>>(
        xr, wdq, cQ, MM, 4096, 1024, 0, 0, 0, 0, 1, 4096);
    // 2. qCR = cQ @ [W_UQ|W_QR]     (8192, 1536, 4096)
    GEMM_OUT<<<dim3(1536/128, MM/128, 1), 256, SM_MAIN>>>(
        cQ, wuqr, qCR, MM, 1536, 4096, 0, 0, 0, 0, 1, 1536);
    // 3. cKV = x @ W_DKV            (8192, 256, 1024)
    GEMM_MAIN<<<dim3(256/128, MM/128, 1), 256, SM_MAIN>>>(
        xr, wdkv, cKV, MM, 256, 1024, 0, 0, 0, 0, 1, 256);
    // 4. kCv = cKV @ [W_UK|W_UV]    (8192, 2048, 256)
    GEMM_OUT<<<dim3(2048/128, MM/128, 1), 256, SM_MAIN>>>(
        cKV, wukv, kCv, MM, 2048, 256, 0, 0, 0, 0, 1, 2048);
    // 5. kR = x @ W_KR              (8192, 32, 1024)
    gemm_n32<<<(MM*32)/256, 256>>>(xr, wkr, kR, MM, 1024);

    // 6. assemble Q/K/V with RoPE scale (rounds outputs to tf32)
    {
        long long total = (long long)BH * Tt * Dd;
        int blocks = (int)((total + 255) / 256);
        assemble_qkv<<<blocks, 256>>>(qCR, kCv, kR, Q, K, V);
    }

    // 7. S = Q @ K^T  batched over 64 (b,h), causal tile skip  (2048,2048,96)
    GEMM_QK<<<dim3(Tt/128, Tt/128, BH), 256, SM_QK>>>(
        Q, K, S, Tt, Tt, Dd,
        (long long)Tt*Dd, (long long)Tt*Dd,
        (long long)Tt*Tt, 0, 1, Tt);

    // 8. causal softmax over rows of S (rounds P to tf32)
    softmax_causal<<<BH*Tt, 256>>>(S, 1.0f / sqrtf((float)Dd));

    // 9. Y = P @ V  batched, causal k-bound, writes (B,T,H*HS) layout
    GEMM_PV<<<dim3(1, Tt/128, BH), 256, SM_PV>>>(
        S, V, Y, Tt, HS_, Tt,
        (long long)Tt*Tt, (long long)Tt*HS_,
        (long long)Tt*Cc_, (long long)HS_, Hh, Cc_);

    // 10. out = Y @ W_O             (8192, 1024, 1024)
    GEMM_OUT<<<dim3(1024/128, MM/128, 1), 256, SM_MAIN>>>(
        Y, wo, out, MM, 1024, 1024, 0, 0, 0, 0, 1, 1024);
}

// round 9
// speedup vs baseline: 4.1902x; 1.1886x over previous
#include <cuda_runtime.h>
#include <cuda_bf16.h>
#include <math.h>
#include <stdint.h>

// ---------------------------------------------------------------------------
// MLA attention: TF32 mma + cp.async GEMMs + fused flash attention.
// B=4, T=2048, C=1024, H=16, HS=64, DHR=32, D=HS+DHR=96, M=B*T=8192
// ---------------------------------------------------------------------------

#define Bb   4
#define Tt   2048
#define Cc_  1024
#define Hh   16
#define HS_  64
#define DHR_ 32
#define Dd   96
#define MM   (Bb*Tt)          // 8192
#define BH   (Bb*Hh)          // 64

// ------------------------- scratch (static device) -------------------------
__device__ float g_cQ  [(size_t)MM*4096];
__device__ float g_cKV [(size_t)MM*256];
__device__ float g_qCR [(size_t)MM*1536];   // qC | qR
__device__ float g_kCv [(size_t)MM*2048];   // kC | v
__device__ float g_kR  [(size_t)MM*32];
__device__ float g_Q   [(size_t)BH*Tt*Dd];
__device__ float g_K   [(size_t)BH*Tt*Dd];
__device__ float g_V   [(size_t)BH*Tt*HS_];
__device__ float g_Y   [(size_t)MM*1024];
// tf32-rounded copies of inputs
__device__ float g_x    [(size_t)MM*Cc_];
__device__ float g_wdq  [(size_t)Cc_*4096];
__device__ float g_wuqr [(size_t)4096*1536];
__device__ float g_wdkv [(size_t)Cc_*256];
__device__ float g_wukv [(size_t)256*2048];
__device__ float g_wkr  [(size_t)Cc_*32];
__device__ float g_wo   [(size_t)Cc_*Cc_];

// ------------------------- helpers -----------------------------------------
__device__ __forceinline__ float to_tf32(float f) {
    uint32_t u;
    asm("cvt.rna.tf32.f32 %0, %1;" : "=r"(u) : "f"(f));
    return __uint_as_float(u);
}

__device__ __forceinline__ void mma_tf32(float* c, const uint32_t* a, const uint32_t* b) {
    asm volatile(
        "mma.sync.aligned.m16n8k8.row.col.f32.tf32.tf32.f32 "
        "{%0,%1,%2,%3}, {%4,%5,%6,%7}, {%8,%9}, {%0,%1,%2,%3};"
        : "+f"(c[0]), "+f"(c[1]), "+f"(c[2]), "+f"(c[3])
        : "r"(a[0]), "r"(a[1]), "r"(a[2]), "r"(a[3]),
          "r"(b[0]), "r"(b[1]));
}

__device__ __forceinline__ void cp16(uint32_t dst, const void* src) {
    asm volatile("cp.async.cg.shared.global [%0], [%1], 16;" :: "r"(dst), "l"(src));
}
__device__ __forceinline__ uint32_t smem_u32(const void* p) {
    return (uint32_t)__cvta_generic_to_shared(p);
}

// ------------------- TF32 pipelined tensor-core GEMM -----------------------
template<int BM,int BN,int BK,int WM,int WN,bool TRB,bool CAUSAL,bool ROUND>
__global__ void __launch_bounds__(256, 2)
gemm_tc(const float* __restrict__ A,
        const float* __restrict__ B,
        float* __restrict__ C,
        int M, int N, int K,
        long long sA, long long sB,
        long long cB, long long cH, int Hdiv, int ldc)
{
    constexpr int WARPS_N = BN/WN;
    constexpr int THREADS = 256;
    constexpr int MT = WM/16;
    constexpr int NT = WN/8;
    constexpr int ASTR  = BK+4;
    constexpr int BROWS = TRB ? BN : BK;
    constexpr int BSTR  = (TRB ? BK : BN) + 4;
    constexpr int ASZ = BM*ASTR;
    constexpr int BSZ = BROWS*BSTR;

    const int bm = blockIdx.y * BM;
    const int bn = blockIdx.x * BN;
    if (CAUSAL && TRB && bn > bm + BM - 1) return;

    extern __shared__ float smem[];
    float* As = smem;
    float* Bs = smem + 2*ASZ;
    const uint32_t s_as = smem_u32(As);
    const uint32_t s_bs = smem_u32(Bs);

    const int z = blockIdx.z;
    A += (long long)z * sA;
    B += (long long)z * sB;
    C += (long long)(z / Hdiv) * cB + (long long)(z % Hdiv) * cH;

    const int tid  = threadIdx.x;
    const int warp = tid >> 5;
    const int lane = tid & 31;
    const int lr   = lane >> 2;
    const int lc   = lane & 3;
    const int wm0  = (warp / WARPS_N) * WM;
    const int wn0  = (warp % WARPS_N) * WN;

    float acc[MT][NT][4];
    #pragma unroll
    for (int i = 0; i < MT; i++)
        #pragma unroll
        for (int j = 0; j < NT; j++)
            #pragma unroll
            for (int r = 0; r < 4; r++) acc[i][j][r] = 0.f;

    const int kend   = (CAUSAL && !TRB) ? min(K, bm + BM) : K;
    const int ntiles = kend / BK;

    auto load_tile = [&](int kt, int buf) {
        const int k0 = kt * BK;
        #pragma unroll
        for (int i = tid; i < BM*(BK/4); i += THREADS) {
            int m  = i / (BK/4);
            int kq = i % (BK/4);
            cp16(s_as + (uint32_t)(buf*ASZ + m*ASTR + kq*4)*4u,
                 A + (long long)(bm+m)*K + k0 + kq*4);
        }
        if (!TRB) {
            #pragma unroll
            for (int i = tid; i < BK*(BN/4); i += THREADS) {
                int kr = i / (BN/4);
                int nq = i % (BN/4);
                cp16(s_bs + (uint32_t)(buf*BSZ + kr*BSTR + nq*4)*4u,
                     B + (long long)(k0+kr)*N + bn + nq*4);
            }
        } else {
            #pragma unroll
            for (int i = tid; i < BN*(BK/4); i += THREADS) {
                int nr = i / (BK/4);
                int kq = i % (BK/4);
                cp16(s_bs + (uint32_t)(buf*BSZ + nr*BSTR + kq*4)*4u,
                     B + (long long)(bn+nr)*K + k0 + kq*4);
            }
        }
    };

    load_tile(0, 0);
    asm volatile("cp.async.commit_group;");

    for (int kt = 0; kt < ntiles; kt++) {
        const int buf = kt & 1;
        if (kt + 1 < ntiles) {
            load_tile(kt+1, buf^1);
            asm volatile("cp.async.commit_group;");
            asm volatile("cp.async.wait_group 1;");
        } else {
            asm volatile("cp.async.wait_group 0;");
        }
        __syncthreads();

        const float* Atile = As + buf*ASZ;
        const float* Btile = Bs + buf*BSZ;

        #pragma unroll
        for (int kk = 0; kk < BK; kk += 8) {
            uint32_t a[MT][4], b[NT][2];
            #pragma unroll
            for (int mt = 0; mt < MT; mt++) {
                const float* ap = Atile + (wm0 + mt*16 + lr)*ASTR + kk + lc;
                a[mt][0] = __float_as_uint(ap[0]);
                a[mt][1] = __float_as_uint(ap[8*ASTR]);
                a[mt][2] = __float_as_uint(ap[4]);
                a[mt][3] = __float_as_uint(ap[8*ASTR + 4]);
            }
            #pragma unroll
            for (int nt = 0; nt < NT; nt++) {
                if (!TRB) {
                    const float* bp = Btile + (kk+lc)*BSTR + wn0 + nt*8 + lr;
                    b[nt][0] = __float_as_uint(bp[0]);
                    b[nt][1] = __float_as_uint(bp[4*BSTR]);
                } else {
                    const float* bp = Btile + (wn0 + nt*8 + lr)*BSTR + kk + lc;
                    b[nt][0] = __float_as_uint(bp[0]);
                    b[nt][1] = __float_as_uint(bp[4]);
                }
            }
            #pragma unroll
            for (int mt = 0; mt < MT; mt++)
                #pragma unroll
                for (int nt = 0; nt < NT; nt++)
                    mma_tf32(acc[mt][nt], a[mt], b[nt]);
        }
        __syncthreads();
    }

    #pragma unroll
    for (int mt = 0; mt < MT; mt++) {
        int row0 = bm + wm0 + mt*16 + lr;
        #pragma unroll
        for (int nt = 0; nt < NT; nt++) {
            int col = bn + wn0 + nt*8 + 2*lc;
            float2 v0, v1;
            if (ROUND) {
                v0 = make_float2(to_tf32(acc[mt][nt][0]), to_tf32(acc[mt][nt][1]));
                v1 = make_float2(to_tf32(acc[mt][nt][2]), to_tf32(acc[mt][nt][3]));
            } else {
                v0 = make_float2(acc[mt][nt][0], acc[mt][nt][1]);
                v1 = make_float2(acc[mt][nt][2], acc[mt][nt][3]);
            }
            *(float2*)(C + (long long)row0*ldc + col)     = v0;
            *(float2*)(C + (long long)(row0+8)*ldc + col) = v1;
        }
    }
}

// ---------------------- fused flash attention ------------------------------
// grid (16 qtiles, 64 bh), 256 threads. Q tile 128x96 resident; K/V tiles of
// 64 rows double-buffered; online softmax; P via warp-private smem rows.
// Writes Y in (B,T,H*64) layout, tf32-rounded.
__global__ void __launch_bounds__(256, 1)
flash_attn(const float* __restrict__ Qg, const float* __restrict__ Kg,
           const float* __restrict__ Vg, float* __restrict__ Yg, float scl)
{
    constexpr int QSTR = 100, KSTR = 100, VSTR = 68, PSTR = 68;
    extern __shared__ float sm[];
    float* sQ = sm;                      // 128*100
    float* sK = sQ + 128*QSTR;           // 2*64*100
    float* sV = sK + 2*64*KSTR;          // 2*64*68
    float* sP = sV + 2*64*VSTR;          // 128*68
    const uint32_t uQ = smem_u32(sQ), uK = smem_u32(sK), uV = smem_u32(sV);

    const int qi = blockIdx.x, bh = blockIdx.y;
    const int tid = threadIdx.x, warp = tid >> 5, lane = tid & 31;
    const int lr = lane >> 2, lc = lane & 3;
    const int wm0 = warp * 16;

    const float* Qp = Qg + ((long long)bh*Tt + qi*128)*Dd;
    const float* Kp = Kg + (long long)bh*Tt*Dd;
    const float* Vp = Vg + (long long)bh*Tt*HS_;

    // Q: 128 rows x 96 floats
    for (int i = tid; i < 128*24; i += 256) {
        int r = i/24, cq = i%24;
        cp16(uQ + (uint32_t)(r*QSTR + cq*4)*4u, Qp + (long long)r*Dd + cq*4);
    }
    auto load_kv = [&](int j, int buf){
        const float* kp = Kp + (long long)j*64*Dd;
        for (int i = tid; i < 64*24; i += 256) {
            int r = i/24, cq = i%24;
            cp16(uK + (uint32_t)(buf*64*KSTR + r*KSTR + cq*4)*4u, kp + (long long)r*Dd + cq*4);
        }
        const float* vp = Vp + (long long)j*64*HS_;
        for (int i = tid; i < 64*16; i += 256) {
            int r = i/16, cq = i%16;
            cp16(uV + (uint32_t)(buf*64*VSTR + r*VSTR + cq*4)*4u, vp + (long long)r*HS_ + cq*4);
        }
    };
    load_kv(0, 0);
    asm volatile("cp.async.commit_group;");

    float oacc[8][4];
    #pragma unroll
    for (int n = 0; n < 8; n++)
        #pragma unroll
        for (int r = 0; r < 4; r++) oacc[n][r] = 0.f;
    float m_lo = -1e30f, m_hi = -1e30f, l_lo = 0.f, l_hi = 0.f;

    const int njt = 2*qi + 2;
    const int q_lo = qi*128 + wm0 + lr;
    const int q_hi = q_lo + 8;

    for (int j = 0; j < njt; j++) {
        const int buf = j & 1;
        if (j + 1 < njt) {
            load_kv(j+1, buf^1);
            asm volatile("cp.async.commit_group;");
            asm volatile("cp.async.wait_group 1;");
        } else {
            asm volatile("cp.async.wait_group 0;");
        }
        __syncthreads();

        const float* Ktile = sK + buf*64*KSTR;
        const float* Vtile = sV + buf*64*VSTR;

        // S = Q @ K^T  (warp rows wm0..wm0+15, all 64 cols)
        float sacc[8][4];
        #pragma unroll
        for (int n = 0; n < 8; n++)
            #pragma unroll
            for (int r = 0; r < 4; r++) sacc[n][r] = 0.f;

        #pragma unroll
        for (int kk = 0; kk < Dd; kk += 8) {
            uint32_t a[4], b[8][2];
            const float* ap = sQ + (wm0+lr)*QSTR + kk + lc;
            a[0] = __float_as_uint(ap[0]);
            a[1] = __float_as_uint(ap[8*QSTR]);
            a[2] = __float_as_uint(ap[4]);
            a[3] = __float_as_uint(ap[8*QSTR+4]);
            #pragma unroll
            for (int n = 0; n < 8; n++) {
                const float* bp = Ktile + (n*8+lr)*KSTR + kk + lc;
                b[n][0] = __float_as_uint(bp[0]);
                b[n][1] = __float_as_uint(bp[4]);
            }
            #pragma unroll
            for (int n = 0; n < 8; n++) mma_tf32(sacc[n], a, b[n]);
        }

        // scale + causal mask (only diagonal tiles can be masked)
        const bool need_mask = (j >= 2*qi);
        float tmax_lo = -1e30f, tmax_hi = -1e30f;
        #pragma unroll
        for (int n = 0; n < 8; n++) {
            const int c0 = j*64 + n*8 + 2*lc;
            #pragma unroll
            for (int e = 0; e < 2; e++) {
                float slo = sacc[n][e]   * scl;
                float shi = sacc[n][2+e] * scl;
                if (need_mask) {
                    if (c0+e > q_lo) slo = -1e30f;
                    if (c0+e > q_hi) shi = -1e30f;
                }
                sacc[n][e]   = slo;
                sacc[n][2+e] = shi;
                tmax_lo = fmaxf(tmax_lo, slo);
                tmax_hi = fmaxf(tmax_hi, shi);
            }
        }
        tmax_lo = fmaxf(tmax_lo, __shfl_xor_sync(0xffffffffu, tmax_lo, 1));
        tmax_lo = fmaxf(tmax_lo, __shfl_xor_sync(0xffffffffu, tmax_lo, 2));
        tmax_hi = fmaxf(tmax_hi, __shfl_xor_sync(0xffffffffu, tmax_hi, 1));
        tmax_hi = fmaxf(tmax_hi, __shfl_xor_sync(0xffffffffu, tmax_hi, 2));

        const float mn_lo = fmaxf(m_lo, tmax_lo);
        const float mn_hi = fmaxf(m_hi, tmax_hi);
        const float al_lo = __expf(m_lo - mn_lo);
        const float al_hi = __expf(m_hi - mn_hi);
        m_lo = mn_lo; m_hi = mn_hi;

        float sum_lo = 0.f, sum_hi = 0.f;
        #pragma unroll
        for (int n = 0; n < 8; n++) {
            #pragma unroll
            for (int e = 0; e < 2; e++) {
                float plo = __expf(sacc[n][e]   - mn_lo);
                float phi = __expf(sacc[n][2+e] - mn_hi);
                sacc[n][e]   = plo;
                sacc[n][2+e] = phi;
                sum_lo += plo;
                sum_hi += phi;
            }
        }
        sum_lo += __shfl_xor_sync(0xffffffffu, sum_lo, 1);
        sum_lo += __shfl_xor_sync(0xffffffffu, sum_lo, 2);
        sum_hi += __shfl_xor_sync(0xffffffffu, sum_hi, 1);
        sum_hi += __shfl_xor_sync(0xffffffffu, sum_hi, 2);
        l_lo = l_lo*al_lo + sum_lo;
        l_hi = l_hi*al_hi + sum_hi;

        #pragma unroll
        for (int n = 0; n < 8; n++) {
            oacc[n][0] *= al_lo; oacc[n][1] *= al_lo;
            oacc[n][2] *= al_hi; oacc[n][3] *= al_hi;
        }

        // P -> smem (warp-private rows), tf32-rounded
        #pragma unroll
        for (int n = 0; n < 8; n++) {
            float2 v0 = make_float2(to_tf32(sacc[n][0]), to_tf32(sacc[n][1]));
            float2 v1 = make_float2(to_tf32(sacc[n][2]), to_tf32(sacc[n][3]));
            *(float2*)(sP + (wm0+lr)*PSTR   + n*8 + 2*lc) = v0;
            *(float2*)(sP + (wm0+lr+8)*PSTR + n*8 + 2*lc) = v1;
        }
        __syncwarp();

        // O += P @ V
        #pragma unroll
        for (int kk = 0; kk < 64; kk += 8) {
            uint32_t a[4], b[8][2];
            const float* ap = sP + (wm0+lr)*PSTR + kk + lc;
            a[0] = __float_as_uint(ap[0]);
            a[1] = __float_as_uint(ap[8*PSTR]);
            a[2] = __float_as_uint(ap[4]);
            a[3] = __float_as_uint(ap[8*PSTR+4]);
            #pragma unroll
            for (int n = 0; n < 8; n++) {
                const float* bp = Vtile + (kk+lc)*VSTR + n*8 + lr;
                b[n][0] = __float_as_uint(bp[0]);
                b[n][1] = __float_as_uint(bp[4*VSTR]);
            }
            #pragma unroll
            for (int n = 0; n < 8; n++) mma_tf32(oacc[n], a, b[n]);
        }
        __syncthreads();
    }

    // epilogue: Y (B,T,H*64), tf32-rounded (feeds W_O GEMM)
    const int b = bh >> 4, h = bh & 15;
    const float inv_lo = 1.f / l_lo, inv_hi = 1.f / l_hi;
    const long long row0 = (long long)(b*Tt + qi*128 + wm0 + lr)*1024 + h*64;
    #pragma unroll
    for (int n = 0; n < 8; n++) {
        const int c = n*8 + 2*lc;
        float2 v0 = make_float2(to_tf32(oacc[n][0]*inv_lo), to_tf32(oacc[n][1]*inv_lo));
        float2 v1 = make_float2(to_tf32(oacc[n][2]*inv_hi), to_tf32(oacc[n][3]*inv_hi));
        *(float2*)(Yg + row0 + c)          = v0;
        *(float2*)(Yg + row0 + 8*1024 + c) = v1;
    }
}

// ------------------------- tf32 round-copy ---------------------------------
__global__ void round_copy(const float* __restrict__ src, float* __restrict__ dst, int n)
{
    for (int i = blockIdx.x*blockDim.x + threadIdx.x; i < n;
         i += gridDim.x*blockDim.x)
        dst[i] = to_tf32(src[i]);
}

__global__ void round_copy_off(const float* __restrict__ src, float* __restrict__ dst,
                               int rows, int cols, int ld, int off)
{
    long long n = (long long)rows*cols;
    for (long long i = (long long)blockIdx.x*blockDim.x + threadIdx.x; i < n;
         i += (long long)gridDim.x*blockDim.x) {
        int r = (int)(i / cols);
        int c = (int)(i % cols);
        dst[(long long)r*ld + off + c] = to_tf32(src[i]);
    }
}

// ------------------------- small-N GEMM (k_R, N=32) ------------------------
__global__ void gemm_n32(const float* __restrict__ A, const float* __restrict__ Bw,
                         float* __restrict__ Cm, int M, int K)
{
    int gw   = (blockIdx.x * blockDim.x + threadIdx.x) >> 5;
    int lane = threadIdx.x & 31;
    if (gw >= M) return;
    const float* a = A + (long long)gw * K;
    float acc = 0.f;
    #pragma unroll 8
    for (int k = 0; k < K; k++)
        acc += a[k] * Bw[k*32 + lane];
    Cm[(long long)gw*32 + lane] = acc;
}

// --------------------- assemble Q/K/V with RoPE scale ----------------------
__constant__ float c_inv[16] = {
    1.0f, 0.5623413251903491f, 0.31622776601683794f, 0.17782794100389228f,
    0.1f, 0.05623413251903491f, 0.031622776601683794f, 0.017782794100389228f,
    0.01f, 0.005623413251903491f, 0.0031622776601683794f, 0.0017782794100389228f,
    0.001f, 0.0005623413251903491f, 0.00031622776601683794f, 0.00017782794100389228f
};

__global__ void assemble_qkv(const float* __restrict__ qCR,
                             const float* __restrict__ kCv,
                             const float* __restrict__ kR,
                             float* __restrict__ Q, float* __restrict__ K,
                             float* __restrict__ V)
{
    const long long total = (long long)BH * Tt * Dd;
    for (long long idx = (long long)blockIdx.x * blockDim.x + threadIdx.x;
         idx < total; idx += (long long)gridDim.x * blockDim.x)
    {
        int d = (int)(idx % Dd);
        long long r = idx / Dd;            // (b,h,t)
        int t = (int)(r % Tt);
        long long r2 = r / Tt;             // (b,h)
        int h = (int)(r2 % Hh);
        int b = (int)(r2 / Hh);
        long long bt = (long long)b * Tt + t;

        float qv, kv;
        if (d < HS_) {
            qv = qCR[bt * 1536 + h * HS_ + d];
            kv = kCv[bt * 2048 + h * HS_ + d];
            V[(r2 * Tt + t) * HS_ + d] = to_tf32(kCv[bt * 2048 + 1024 + h * HS_ + d]);
        } else {
            int j  = d - HS_;
            int fi = j & 15;
            float ang = (float)t * c_inv[fi];
            float s_, co;
            sincosf(ang, &s_, &co);
            float sc = co + s_;
            qv = qCR[bt * 1536 + 1024 + h * DHR_ + j] * sc;
            kv = kR[bt * 32 + j] * sc;
        }
        Q[idx] = to_tf32(qv);
        K[idx] = to_tf32(kv);
    }
}

// ---------------------------------------------------------------------------
extern "C" void kernel_launch(void* const* d_in, const int* in_sizes, int n_in,
                              void* d_out, int out_size)
{
    const float* x     = (const float*)d_in[0];
    const float* W_DQ  = (const float*)d_in[1];
    const float* W_UQ  = (const float*)d_in[2];
    const float* W_DKV = (const float*)d_in[3];
    const float* W_UK  = (const float*)d_in[4];
    const float* W_UV  = (const float*)d_in[5];
    const float* W_QR  = (const float*)d_in[6];
    const float* W_KR  = (const float*)d_in[7];
    const float* W_O   = (const float*)d_in[8];
    float* out = (float*)d_out;

    float *cQ,*cKV,*qCR,*kCv,*kR,*Q,*K,*V,*Y;
    float *xr,*wdq,*wuqr,*wdkv,*wukv,*wkr,*wo;
    cudaGetSymbolAddress((void**)&cQ,  g_cQ);
    cudaGetSymbolAddress((void**)&cKV, g_cKV);
    cudaGetSymbolAddress((void**)&qCR, g_qCR);
    cudaGetSymbolAddress((void**)&kCv, g_kCv);
    cudaGetSymbolAddress((void**)&kR,  g_kR);
    cudaGetSymbolAddress((void**)&Q,   g_Q);
    cudaGetSymbolAddress((void**)&K,   g_K);
    cudaGetSymbolAddress((void**)&V,   g_V);
    cudaGetSymbolAddress((void**)&Y,   g_Y);
    cudaGetSymbolAddress((void**)&xr,  g_x);
    cudaGetSymbolAddress((void**)&wdq, g_wdq);
    cudaGetSymbolAddress((void**)&wuqr,g_wuqr);
    cudaGetSymbolAddress((void**)&wdkv,g_wdkv);
    cudaGetSymbolAddress((void**)&wukv,g_wukv);
    cudaGetSymbolAddress((void**)&wkr, g_wkr);
    cudaGetSymbolAddress((void**)&wo,  g_wo);

    const int SM_MAIN = (2*128*(32+4) + 2*32*(128+4)) * 4;
    const int SM_FLASH = (128*100 + 2*64*100 + 2*64*68 + 128*68) * 4;  // 172032

    #define GEMM_MAIN gemm_tc<128,128,32,64,32,false,false,true>
    #define GEMM_OUT  gemm_tc<128,128,32,64,32,false,false,false>

    cudaFuncSetAttribute(GEMM_MAIN, cudaFuncAttributeMaxDynamicSharedMemorySize, SM_MAIN);
    cudaFuncSetAttribute(GEMM_OUT,  cudaFuncAttributeMaxDynamicSharedMemorySize, SM_MAIN);
    cudaFuncSetAttribute(flash_attn, cudaFuncAttributeMaxDynamicSharedMemorySize, SM_FLASH);

    // 0. pre-round inputs to tf32 (with weight concat packing)
    round_copy<<<1024,256>>>(x,     xr,   MM*Cc_);
    round_copy<<<1024,256>>>(W_DQ,  wdq,  Cc_*4096);
    round_copy_off<<<1024,256>>>(W_UQ, wuqr, 4096, 1024, 1536, 0);
    round_copy_off<<<512, 256>>>(W_QR, wuqr, 4096, 512,  1536, 1024);
    round_copy<<<256, 256>>>(W_DKV, wdkv, Cc_*256);
    round_copy_off<<<256, 256>>>(W_UK, wukv, 256, 1024, 2048, 0);
    round_copy_off<<<256, 256>>>(W_UV, wukv, 256, 1024, 2048, 1024);
    round_copy<<<64,  256>>>(W_KR,  wkr,  Cc_*32);
    round_copy<<<512, 256>>>(W_O,   wo,   Cc_*Cc_);

    // 1. cQ = x @ W_DQ              (8192, 4096, 1024)
    GEMM_MAIN<<<dim3(4096/128, MM/128, 1), 256, SM_MAIN>>>(
        xr, wdq, cQ, MM, 4096, 1024, 0, 0, 0, 0, 1, 4096);
    // 2. qCR = cQ @ [W_UQ|W_QR]     (8192, 1536, 4096)
    GEMM_OUT<<<dim3(1536/128, MM/128, 1), 256, SM_MAIN>>>(
        cQ, wuqr, qCR, MM, 1536, 4096, 0, 0, 0, 0, 1, 1536);
    // 3. cKV = x @ W_DKV            (8192, 256, 1024)
    GEMM_MAIN<<<dim3(256/128, MM/128, 1), 256, SM_MAIN>>>(
        xr, wdkv, cKV, MM, 256, 1024, 0, 0, 0, 0, 1, 256);
    // 4. kCv = cKV @ [W_UK|W_UV]    (8192, 2048, 256)
    GEMM_OUT<<<dim3(2048/128, MM/128, 1), 256, SM_MAIN>>>(
        cKV, wukv, kCv, MM, 2048, 256, 0, 0, 0, 0, 1, 2048);
    // 5. kR = x @ W_KR              (8192, 32, 1024)
    gemm_n32<<<(MM*32)/256, 256>>>(xr, wkr, kR, MM, 1024);

    // 6. assemble Q/K/V with RoPE scale
    {
        long long total = (long long)BH * Tt * Dd;
        int blocks = (int)((total + 255) / 256);
        assemble_qkv<<<blocks, 256>>>(qCR, kCv, kR, Q, K, V);
    }

    // 7. fused flash attention -> Y (B,T,H*64)
    flash_attn<<<dim3(16, BH), 256, SM_FLASH>>>(Q, K, V, Y, 1.0f/sqrtf((float)Dd));

    // 8. out = Y @ W_O              (8192, 1024, 1024)
    GEMM_OUT<<<dim3(1024/128, MM/128, 1), 256, SM_MAIN>>>(
        Y, wo, out, MM, 1024, 1024, 0, 0, 0, 0, 1, 1024);
}

// round 12
// speedup vs baseline: 4.3014x; 1.0265x over previous
#include <cuda_runtime.h>
#include <cuda_bf16.h>
#include <math.h>
#include <stdint.h>

// ---------------------------------------------------------------------------
// MLA attention: TF32 mma + 3-stage cp.async GEMMs + fused flash attention.
// B=4, T=2048, C=1024, H=16, HS=64, DHR=32, D=HS+DHR=96, M=B*T=8192
// ---------------------------------------------------------------------------

#define Bb   4
#define Tt   2048
#define Cc_  1024
#define Hh   16
#define HS_  64
#define DHR_ 32
#define Dd   96
#define MM   (Bb*Tt)          // 8192
#define BH   (Bb*Hh)          // 64

// ------------------------- scratch (static device) -------------------------
__device__ float g_cQ  [(size_t)MM*4096];
__device__ float g_cKV [(size_t)MM*256];
__device__ float g_qCR [(size_t)MM*1536];   // qC | qR
__device__ float g_kCv [(size_t)MM*2048];   // kC | v
__device__ float g_kR  [(size_t)MM*32];
__device__ float g_Q   [(size_t)BH*Tt*Dd];
__device__ float g_K   [(size_t)BH*Tt*Dd];
__device__ float g_V   [(size_t)BH*Tt*HS_];
__device__ float g_Y   [(size_t)MM*1024];
// tf32-rounded copies of inputs
__device__ float g_x    [(size_t)MM*Cc_];
__device__ float g_wdq  [(size_t)Cc_*4096];
__device__ float g_wuqr [(size_t)4096*1536];
__device__ float g_wdkv [(size_t)Cc_*256];
__device__ float g_wukv [(size_t)256*2048];
__device__ float g_wkr  [(size_t)Cc_*32];
__device__ float g_wo   [(size_t)Cc_*Cc_];

// ------------------------- helpers -----------------------------------------
__device__ __forceinline__ float to_tf32(float f) {
    uint32_t u;
    asm("cvt.rna.tf32.f32 %0, %1;" : "=r"(u) : "f"(f));
    return __uint_as_float(u);
}

__device__ __forceinline__ void mma_tf32(float* c, const uint32_t* a, const uint32_t* b) {
    asm volatile(
        "mma.sync.aligned.m16n8k8.row.col.f32.tf32.tf32.f32 "
        "{%0,%1,%2,%3}, {%4,%5,%6,%7}, {%8,%9}, {%0,%1,%2,%3};"
        : "+f"(c[0]), "+f"(c[1]), "+f"(c[2]), "+f"(c[3])
        : "r"(a[0]), "r"(a[1]), "r"(a[2]), "r"(a[3]),
          "r"(b[0]), "r"(b[1]));
}

__device__ __forceinline__ void cp16(uint32_t dst, const void* src) {
    asm volatile("cp.async.cg.shared.global [%0], [%1], 16;" :: "r"(dst), "l"(src));
}
__device__ __forceinline__ uint32_t smem_u32(const void* p) {
    return (uint32_t)__cvta_generic_to_shared(p);
}

// ------------- TF32 3-stage pipelined tensor-core GEMM ---------------------
// C = A(MxK) * B(KxN).   A,B pre-rounded to tf32.
// ROUND: round C to tf32 on store (when C feeds a later GEMM/flash).
template<int BM,int BN,int BK,int WM,int WN,bool ROUND>
__global__ void __launch_bounds__(256, 2)
gemm_tc(const float* __restrict__ A,
        const float* __restrict__ B,
        float* __restrict__ C,
        int M, int N, int K, int ldc)
{
    constexpr int WARPS_N = BN/WN;
    constexpr int THREADS = 256;
    constexpr int MT = WM/16;
    constexpr int NT = WN/8;
    constexpr int ASTR = BK+4;      // 36: A-frag reads conflict-free
    constexpr int BSTR = BN+8;      // 136 ≡ 8 (mod 32): B-frag reads conflict-free
    constexpr int ASZ = BM*ASTR;
    constexpr int BSZ = BK*BSTR;

    const int bm = blockIdx.y * BM;
    const int bn = blockIdx.x * BN;

    extern __shared__ float smem[];
    float* As = smem;                  // [3][ASZ]
    float* Bs = smem + 3*ASZ;          // [3][BSZ]
    const uint32_t s_as = smem_u32(As);
    const uint32_t s_bs = smem_u32(Bs);

    const int tid  = threadIdx.x;
    const int warp = tid >> 5;
    const int lane = tid & 31;
    const int lr   = lane >> 2;
    const int lc   = lane & 3;
    const int wm0  = (warp / WARPS_N) * WM;
    const int wn0  = (warp % WARPS_N) * WN;

    float acc[MT][NT][4];
    #pragma unroll
    for (int i = 0; i < MT; i++)
        #pragma unroll
        for (int j = 0; j < NT; j++)
            #pragma unroll
            for (int r = 0; r < 4; r++) acc[i][j][r] = 0.f;

    const int ntiles = K / BK;

    auto load_tile = [&](int kt, int buf) {
        const int k0 = kt * BK;
        #pragma unroll
        for (int i = tid; i < BM*(BK/4); i += THREADS) {
            int m  = i / (BK/4);
            int kq = i % (BK/4);
            cp16(s_as + (uint32_t)(buf*ASZ + m*ASTR + kq*4)*4u,
                 A + (long long)(bm+m)*K + k0 + kq*4);
        }
        #pragma unroll
        for (int i = tid; i < BK*(BN/4); i += THREADS) {
            int kr = i / (BN/4);
            int nq = i % (BN/4);
            cp16(s_bs + (uint32_t)(buf*BSZ + kr*BSTR + nq*4)*4u,
                 B + (long long)(k0+kr)*N + bn + nq*4);
        }
    };

    load_tile(0, 0);
    asm volatile("cp.async.commit_group;");
    if (ntiles > 1) {
        load_tile(1, 1);
        asm volatile("cp.async.commit_group;");
    }

    int buf = 0;
    for (int kt = 0; kt < ntiles; kt++) {
        if (kt + 1 < ntiles) asm volatile("cp.async.wait_group 1;");
        else                 asm volatile("cp.async.wait_group 0;");
        __syncthreads();

        const int nxt = kt + 2;
        if (nxt < ntiles) {
            int b3 = nxt - (nxt/3)*3;
            load_tile(nxt, b3);
            asm volatile("cp.async.commit_group;");
        }

        const float* Atile = As + buf*ASZ;
        const float* Btile = Bs + buf*BSZ;

        #pragma unroll
        for (int kk = 0; kk < BK; kk += 8) {
            uint32_t a[MT][4], b[NT][2];
            #pragma unroll
            for (int mt = 0; mt < MT; mt++) {
                const float* ap = Atile + (wm0 + mt*16 + lr)*ASTR + kk + lc;
                a[mt][0] = __float_as_uint(ap[0]);
                a[mt][1] = __float_as_uint(ap[8*ASTR]);
                a[mt][2] = __float_as_uint(ap[4]);
                a[mt][3] = __float_as_uint(ap[8*ASTR + 4]);
            }
            #pragma unroll
            for (int nt = 0; nt < NT; nt++) {
                const float* bp = Btile + (kk+lc)*BSTR + wn0 + nt*8 + lr;
                b[nt][0] = __float_as_uint(bp[0]);
                b[nt][1] = __float_as_uint(bp[4*BSTR]);
            }
            #pragma unroll
            for (int mt = 0; mt < MT; mt++)
                #pragma unroll
                for (int nt = 0; nt < NT; nt++)
                    mma_tf32(acc[mt][nt], a[mt], b[nt]);
        }
        buf = (buf == 2) ? 0 : buf + 1;
    }

    #pragma unroll
    for (int mt = 0; mt < MT; mt++) {
        int row0 = bm + wm0 + mt*16 + lr;
        #pragma unroll
        for (int nt = 0; nt < NT; nt++) {
            int col = bn + wn0 + nt*8 + 2*lc;
            float2 v0, v1;
            if (ROUND) {
                v0 = make_float2(to_tf32(acc[mt][nt][0]), to_tf32(acc[mt][nt][1]));
                v1 = make_float2(to_tf32(acc[mt][nt][2]), to_tf32(acc[mt][nt][3]));
            } else {
                v0 = make_float2(acc[mt][nt][0], acc[mt][nt][1]);
                v1 = make_float2(acc[mt][nt][2], acc[mt][nt][3]);
            }
            *(float2*)(C + (long long)row0*ldc + col)     = v0;
            *(float2*)(C + (long long)(row0+8)*ldc + col) = v1;
        }
    }
}

// ---------------------- fused flash attention ------------------------------
__global__ void __launch_bounds__(256, 1)
flash_attn(const float* __restrict__ Qg, const float* __restrict__ Kg,
           const float* __restrict__ Vg, float* __restrict__ Yg, float scl)
{
    constexpr int QSTR = 100, KSTR = 100, VSTR = 68, PSTR = 68;
    extern __shared__ float sm[];
    float* sQ = sm;                      // 128*100
    float* sK = sQ + 128*QSTR;           // 2*64*100
    float* sV = sK + 2*64*KSTR;          // 2*64*68
    float* sP = sV + 2*64*VSTR;          // 128*68
    const uint32_t uQ = smem_u32(sQ), uK = smem_u32(sK), uV = smem_u32(sV);

    const int qi = blockIdx.x, bh = blockIdx.y;
    const int tid = threadIdx.x, warp = tid >> 5, lane = tid & 31;
    const int lr = lane >> 2, lc = lane & 3;
    const int wm0 = warp * 16;

    const float* Qp = Qg + ((long long)bh*Tt + qi*128)*Dd;
    const float* Kp = Kg + (long long)bh*Tt*Dd;
    const float* Vp = Vg + (long long)bh*Tt*HS_;

    for (int i = tid; i < 128*24; i += 256) {
        int r = i/24, cq = i%24;
        cp16(uQ + (uint32_t)(r*QSTR + cq*4)*4u, Qp + (long long)r*Dd + cq*4);
    }
    auto load_kv = [&](int j, int buf){
        const float* kp = Kp + (long long)j*64*Dd;
        for (int i = tid; i < 64*24; i += 256) {
            int r = i/24, cq = i%24;
            cp16(uK + (uint32_t)(buf*64*KSTR + r*KSTR + cq*4)*4u, kp + (long long)r*Dd + cq*4);
        }
        const float* vp = Vp + (long long)j*64*HS_;
        for (int i = tid; i < 64*16; i += 256) {
            int r = i/16, cq = i%16;
            cp16(uV + (uint32_t)(buf*64*VSTR + r*VSTR + cq*4)*4u, vp + (long long)r*HS_ + cq*4);
        }
    };
    load_kv(0, 0);
    asm volatile("cp.async.commit_group;");

    float oacc[8][4];
    #pragma unroll
    for (int n = 0; n < 8; n++)
        #pragma unroll
        for (int r = 0; r < 4; r++) oacc[n][r] = 0.f;
    float m_lo = -1e30f, m_hi = -1e30f, l_lo = 0.f, l_hi = 0.f;

    const int njt = 2*qi + 2;
    const int q_lo = qi*128 + wm0 + lr;
    const int q_hi = q_lo + 8;

    for (int j = 0; j < njt; j++) {
        const int buf = j & 1;
        if (j + 1 < njt) {
            load_kv(j+1, buf^1);
            asm volatile("cp.async.commit_group;");
            asm volatile("cp.async.wait_group 1;");
        } else {
            asm volatile("cp.async.wait_group 0;");
        }
        __syncthreads();

        const float* Ktile = sK + buf*64*KSTR;
        const float* Vtile = sV + buf*64*VSTR;

        float sacc[8][4];
        #pragma unroll
        for (int n = 0; n < 8; n++)
            #pragma unroll
            for (int r = 0; r < 4; r++) sacc[n][r] = 0.f;

        #pragma unroll
        for (int kk = 0; kk < Dd; kk += 8) {
            uint32_t a[4], b[8][2];
            const float* ap = sQ + (wm0+lr)*QSTR + kk + lc;
            a[0] = __float_as_uint(ap[0]);
            a[1] = __float_as_uint(ap[8*QSTR]);
            a[2] = __float_as_uint(ap[4]);
            a[3] = __float_as_uint(ap[8*QSTR+4]);
            #pragma unroll
            for (int n = 0; n < 8; n++) {
                const float* bp = Ktile + (n*8+lr)*KSTR + kk + lc;
                b[n][0] = __float_as_uint(bp[0]);
                b[n][1] = __float_as_uint(bp[4]);
            }
            #pragma unroll
            for (int n = 0; n < 8; n++) mma_tf32(sacc[n], a, b[n]);
        }

        const bool need_mask = (j >= 2*qi);
        float tmax_lo = -1e30f, tmax_hi = -1e30f;
        #pragma unroll
        for (int n = 0; n < 8; n++) {
            const int c0 = j*64 + n*8 + 2*lc;
            #pragma unroll
            for (int e = 0; e < 2; e++) {
                float slo = sacc[n][e]   * scl;
                float shi = sacc[n][2+e] * scl;
                if (need_mask) {
                    if (c0+e > q_lo) slo = -1e30f;
                    if (c0+e > q_hi) shi = -1e30f;
                }
                sacc[n][e]   = slo;
                sacc[n][2+e] = shi;
                tmax_lo = fmaxf(tmax_lo, slo);
                tmax_hi = fmaxf(tmax_hi, shi);
            }
        }
        tmax_lo = fmaxf(tmax_lo, __shfl_xor_sync(0xffffffffu, tmax_lo, 1));
        tmax_lo = fmaxf(tmax_lo, __shfl_xor_sync(0xffffffffu, tmax_lo, 2));
        tmax_hi = fmaxf(tmax_hi, __shfl_xor_sync(0xffffffffu, tmax_hi, 1));
        tmax_hi = fmaxf(tmax_hi, __shfl_xor_sync(0xffffffffu, tmax_hi, 2));

        const float mn_lo = fmaxf(m_lo, tmax_lo);
        const float mn_hi = fmaxf(m_hi, tmax_hi);
        const float al_lo = __expf(m_lo - mn_lo);
        const float al_hi = __expf(m_hi - mn_hi);
        m_lo = mn_lo; m_hi = mn_hi;

        float sum_lo = 0.f, sum_hi = 0.f;
        #pragma unroll
        for (int n = 0; n < 8; n++) {
            #pragma unroll
            for (int e = 0; e < 2; e++) {
                float plo = __expf(sacc[n][e]   - mn_lo);
                float phi = __expf(sacc[n][2+e] - mn_hi);
                sacc[n][e]   = plo;
                sacc[n][2+e] = phi;
                sum_lo += plo;
                sum_hi += phi;
            }
        }
        sum_lo += __shfl_xor_sync(0xffffffffu, sum_lo, 1);
        sum_lo += __shfl_xor_sync(0xffffffffu, sum_lo, 2);
        sum_hi += __shfl_xor_sync(0xffffffffu, sum_hi, 1);
        sum_hi += __shfl_xor_sync(0xffffffffu, sum_hi, 2);
        l_lo = l_lo*al_lo + sum_lo;
        l_hi = l_hi*al_hi + sum_hi;

        #pragma unroll
        for (int n = 0; n < 8; n++) {
            oacc[n][0] *= al_lo; oacc[n][1] *= al_lo;
            oacc[n][2] *= al_hi; oacc[n][3] *= al_hi;
        }

        #pragma unroll
        for (int n = 0; n < 8; n++) {
            float2 v0 = make_float2(to_tf32(sacc[n][0]), to_tf32(sacc[n][1]));
            float2 v1 = make_float2(to_tf32(sacc[n][2]), to_tf32(sacc[n][3]));
            *(float2*)(sP + (wm0+lr)*PSTR   + n*8 + 2*lc) = v0;
            *(float2*)(sP + (wm0+lr+8)*PSTR + n*8 + 2*lc) = v1;
        }
        __syncwarp();

        #pragma unroll
        for (int kk = 0; kk < 64; kk += 8) {
            uint32_t a[4], b[8][2];
            const float* ap = sP + (wm0+lr)*PSTR + kk + lc;
            a[0] = __float_as_uint(ap[0]);
            a[1] = __float_as_uint(ap[8*PSTR]);
            a[2] = __float_as_uint(ap[4]);
            a[3] = __float_as_uint(ap[8*PSTR+4]);
            #pragma unroll
            for (int n = 0; n < 8; n++) {
                const float* bp = Vtile + (kk+lc)*VSTR + n*8 + lr;
                b[n][0] = __float_as_uint(bp[0]);
                b[n][1] = __float_as_uint(bp[4*VSTR]);
            }
            #pragma unroll
            for (int n = 0; n < 8; n++) mma_tf32(oacc[n], a, b[n]);
        }
        __syncthreads();
    }

    const int b = bh >> 4, h = bh & 15;
    const float inv_lo = 1.f / l_lo, inv_hi = 1.f / l_hi;
    const long long row0 = (long long)(b*Tt + qi*128 + wm0 + lr)*1024 + h*64;
    #pragma unroll
    for (int n = 0; n < 8; n++) {
        const int c = n*8 + 2*lc;
        float2 v0 = make_float2(to_tf32(oacc[n][0]*inv_lo), to_tf32(oacc[n][1]*inv_lo));
        float2 v1 = make_float2(to_tf32(oacc[n][2]*inv_hi), to_tf32(oacc[n][3]*inv_hi));
        *(float2*)(Yg + row0 + c)          = v0;
        *(float2*)(Yg + row0 + 8*1024 + c) = v1;
    }
}

// ------------------------- tf32 round-copy (float4) ------------------------
__global__ void round_copy(const float4* __restrict__ src, float4* __restrict__ dst, int n4)
{
    for (int i = blockIdx.x*blockDim.x + threadIdx.x; i < n4;
         i += gridDim.x*blockDim.x) {
        float4 v = src[i];
        v.x = to_tf32(v.x); v.y = to_tf32(v.y);
        v.z = to_tf32(v.z); v.w = to_tf32(v.w);
        dst[i] = v;
    }
}

// pack src (rows x cols) into dst rows of width ld at column offset off
__global__ void round_copy_off(const float4* __restrict__ src, float* __restrict__ dst,
                               int rows, int cols4, int ld, int off)
{
    long long n = (long long)rows*cols4;
    for (long long i = (long long)blockIdx.x*blockDim.x + threadIdx.x; i < n;
         i += (long long)gridDim.x*blockDim.x) {
        int r = (int)(i / cols4);
        int c = (int)(i % cols4);
        float4 v = src[i];
        v.x = to_tf32(v.x); v.y = to_tf32(v.y);
        v.z = to_tf32(v.z); v.w = to_tf32(v.w);
        *(float4*)(dst + (long long)r*ld + off + c*4) = v;
    }
}

// ------------------------- small-N GEMM (k_R, N=32) ------------------------
__global__ void gemm_n32(const float* __restrict__ A, const float* __restrict__ Bw,
                         float* __restrict__ Cm, int M, int K)
{
    int gw   = (blockIdx.x * blockDim.x + threadIdx.x) >> 5;
    int lane = threadIdx.x & 31;
    if (gw >= M) return;
    const float* a = A + (long long)gw * K;
    float acc = 0.f;
    #pragma unroll 8
    for (int k = 0; k < K; k++)
        acc += a[k] * Bw[k*32 + lane];
    Cm[(long long)gw*32 + lane] = acc;
}

// --------------------- assemble Q/K/V with RoPE scale ----------------------
__constant__ float c_inv[16] = {
    1.0f, 0.5623413251903491f, 0.31622776601683794f, 0.17782794100389228f,
    0.1f, 0.05623413251903491f, 0.031622776601683794f, 0.017782794100389228f,
    0.01f, 0.005623413251903491f, 0.0031622776601683794f, 0.0017782794100389228f,
    0.001f, 0.0005623413251903491f, 0.00031622776601683794f, 0.00017782794100389228f
};

__global__ void assemble_qkv(const float* __restrict__ qCR,
                             const float* __restrict__ kCv,
                             const float* __restrict__ kR,
                             float* __restrict__ Q, float* __restrict__ K,
                             float* __restrict__ V)
{
    const long long total = (long long)BH * Tt * Dd;
    for (long long idx = (long long)blockIdx.x * blockDim.x + threadIdx.x;
         idx < total; idx += (long long)gridDim.x * blockDim.x)
    {
        int d = (int)(idx % Dd);
        long long r = idx / Dd;            // (b,h,t)
        int t = (int)(r % Tt);
        long long r2 = r / Tt;             // (b,h)
        int h = (int)(r2 % Hh);
        int b = (int)(r2 / Hh);
        long long bt = (long long)b * Tt + t;

        float qv, kv;
        if (d < HS_) {
            qv = qCR[bt * 1536 + h * HS_ + d];
            kv = kCv[bt * 2048 + h * HS_ + d];
            V[(r2 * Tt + t) * HS_ + d] = to_tf32(kCv[bt * 2048 + 1024 + h * HS_ + d]);
        } else {
            int j  = d - HS_;
            int fi = j & 15;
            float ang = (float)t * c_inv[fi];
            float s_, co;
            sincosf(ang, &s_, &co);
            float sc = co + s_;
            qv = qCR[bt * 1536 + 1024 + h * DHR_ + j] * sc;
            kv = kR[bt * 32 + j] * sc;
        }
        Q[idx] = to_tf32(qv);
        K[idx] = to_tf32(kv);
    }
}

// ---------------------------------------------------------------------------
extern "C" void kernel_launch(void* const* d_in, const int* in_sizes, int n_in,
                              void* d_out, int out_size)
{
    const float* x     = (const float*)d_in[0];
    const float* W_DQ  = (const float*)d_in[1];
    const float* W_UQ  = (const float*)d_in[2];
    const float* W_DKV = (const float*)d_in[3];
    const float* W_UK  = (const float*)d_in[4];
    const float* W_UV  = (const float*)d_in[5];
    const float* W_QR  = (const float*)d_in[6];
    const float* W_KR  = (const float*)d_in[7];
    const float* W_O   = (const float*)d_in[8];
    float* out = (float*)d_out;

    float *cQ,*cKV,*qCR,*kCv,*kR,*Q,*K,*V,*Y;
    float *xr,*wdq,*wuqr,*wdkv,*wukv,*wkr,*wo;
    cudaGetSymbolAddress((void**)&cQ,  g_cQ);
    cudaGetSymbolAddress((void**)&cKV, g_cKV);
    cudaGetSymbolAddress((void**)&qCR, g_qCR);
    cudaGetSymbolAddress((void**)&kCv, g_kCv);
    cudaGetSymbolAddress((void**)&kR,  g_kR);
    cudaGetSymbolAddress((void**)&Q,   g_Q);
    cudaGetSymbolAddress((void**)&K,   g_K);
    cudaGetSymbolAddress((void**)&V,   g_V);
    cudaGetSymbolAddress((void**)&Y,   g_Y);
    cudaGetSymbolAddress((void**)&xr,  g_x);
    cudaGetSymbolAddress((void**)&wdq, g_wdq);
    cudaGetSymbolAddress((void**)&wuqr,g_wuqr);
    cudaGetSymbolAddress((void**)&wdkv,g_wdkv);
    cudaGetSymbolAddress((void**)&wukv,g_wukv);
    cudaGetSymbolAddress((void**)&wkr, g_wkr);
    cudaGetSymbolAddress((void**)&wo,  g_wo);

    // 3-stage smem: 3*(128*36 + 32*136)*4 = 107520 bytes
    const int SM_MAIN  = 3*(128*(32+4) + 32*(128+8)) * 4;
    const int SM_FLASH = (128*100 + 2*64*100 + 2*64*68 + 128*68) * 4;  // 172032

    #define GEMM_MAIN gemm_tc<128,128,32,64,32,true>
    #define GEMM_OUT  gemm_tc<128,128,32,64,32,false>

    cudaFuncSetAttribute(GEMM_MAIN, cudaFuncAttributeMaxDynamicSharedMemorySize, SM_MAIN);
    cudaFuncSetAttribute(GEMM_OUT,  cudaFuncAttributeMaxDynamicSharedMemorySize, SM_MAIN);
    cudaFuncSetAttribute(flash_attn, cudaFuncAttributeMaxDynamicSharedMemorySize, SM_FLASH);

    // 0. pre-round inputs to tf32 (float4, saturating grids)
    round_copy<<<2048,256>>>((const float4*)x,    (float4*)xr,   MM*Cc_/4);
    round_copy<<<2048,256>>>((const float4*)W_DQ, (float4*)wdq,  Cc_*4096/4);
    round_copy_off<<<2048,256>>>((const float4*)W_UQ, wuqr, 4096, 1024/4, 1536, 0);
    round_copy_off<<<1024,256>>>((const float4*)W_QR, wuqr, 4096, 512/4,  1536, 1024);
    round_copy<<<512, 256>>>((const float4*)W_DKV,(float4*)wdkv, Cc_*256/4);
    round_copy_off<<<512, 256>>>((const float4*)W_UK, wukv, 256, 1024/4, 2048, 0);
    round_copy_off<<<512, 256>>>((const float4*)W_UV, wukv, 256, 1024/4, 2048, 1024);
    round_copy<<<128, 256>>>((const float4*)W_KR, (float4*)wkr,  Cc_*32/4);
    round_copy<<<1024,256>>>((const float4*)W_O,  (float4*)wo,   Cc_*Cc_/4);

    // 1. cQ = x @ W_DQ              (8192, 4096, 1024)
    GEMM_MAIN<<<dim3(4096/128, MM/128), 256, SM_MAIN>>>(xr, wdq, cQ, MM, 4096, 1024, 4096);
    // 2. qCR = cQ @ [W_UQ|W_QR]     (8192, 1536, 4096)
    GEMM_OUT<<<dim3(1536/128, MM/128), 256, SM_MAIN>>>(cQ, wuqr, qCR, MM, 1536, 4096, 1536);
    // 3. cKV = x @ W_DKV            (8192, 256, 1024)
    GEMM_MAIN<<<dim3(256/128, MM/128), 256, SM_MAIN>>>(xr, wdkv, cKV, MM, 256, 1024, 256);
    // 4. kCv = cKV @ [W_UK|W_UV]    (8192, 2048, 256)
    GEMM_OUT<<<dim3(2048/128, MM/128), 256, SM_MAIN>>>(cKV, wukv, kCv, MM, 2048, 256, 2048);
    // 5. kR = x @ W_KR              (8192, 32, 1024)
    gemm_n32<<<(MM*32)/256, 256>>>(xr, wkr, kR, MM, 1024);

    // 6. assemble Q/K/V with RoPE scale
    {
        long long total = (long long)BH * Tt * Dd;
        int blocks = (int)((total + 255) / 256);
        assemble_qkv<<<blocks, 256>>>(qCR, kCv, kR, Q, K, V);
    }

    // 7. fused flash attention -> Y (B,T,H*64)
    flash_attn<<<dim3(16, BH), 256, SM_FLASH>>>(Q, K, V, Y, 1.0f/sqrtf((float)Dd));

    // 8. out = Y @ W_O              (8192, 1024, 1024)
    GEMM_OUT<<<dim3(1024/128, MM/128), 256, SM_MAIN>>>(Y, wo, out, MM, 1024, 1024, 1024);
}

// round 13
// speedup vs baseline: 6.6160x; 1.5381x over previous
#include <cuda_runtime.h>
#include <cuda_fp16.h>
#include <math.h>
#include <stdint.h>

// ---------------------------------------------------------------------------
// MLA attention: FP16 mma.sync(m16n8k16) + cp.async pipelined GEMMs + fused
// flash attention. fp16 storage everywhere (11-bit mantissa = tf32), fp32 acc.
// B=4, T=2048, C=1024, H=16, HS=64, DHR=32, D=HS+DHR=96, M=B*T=8192
// ---------------------------------------------------------------------------

#define Bb   4
#define Tt   2048
#define Cc_  1024
#define Hh   16
#define HS_  64
#define DHR_ 32
#define Dd   96
#define MM   (Bb*Tt)          // 8192
#define BH   (Bb*Hh)          // 64

// ------------------------- scratch (static device) -------------------------
__device__ __half g_x   [(size_t)MM*1024];
__device__ __half g_cQ  [(size_t)MM*4096];
__device__ __half g_qCR [(size_t)MM*1536];   // qC | qR
__device__ __half g_cKV [(size_t)MM*256];
__device__ __half g_kCv [(size_t)MM*2048];   // kC | v
__device__ float  g_kR  [(size_t)MM*32];
__device__ __half g_Q   [(size_t)BH*Tt*Dd];
__device__ __half g_K   [(size_t)BH*Tt*Dd];
__device__ __half g_V   [(size_t)BH*Tt*HS_]; // key-pair interleaved
__device__ __half g_Y   [(size_t)MM*1024];
// k-pair-interleaved half2 weights: Wp[k/2][n] = (W[k][n], W[k+1][n])
__device__ __half g_wdq [(size_t)1024*4096];
__device__ __half g_wuqr[(size_t)4096*1536];
__device__ __half g_wdkv[(size_t)1024*256];
__device__ __half g_wukv[(size_t)256*2048];
__device__ __half g_wo  [(size_t)1024*1024];

// ------------------------- helpers -----------------------------------------
__device__ __forceinline__ void mma_f16(float* c, const uint32_t* a, const uint32_t* b) {
    asm volatile(
        "mma.sync.aligned.m16n8k16.row.col.f32.f16.f16.f32 "
        "{%0,%1,%2,%3}, {%4,%5,%6,%7}, {%8,%9}, {%0,%1,%2,%3};"
        : "+f"(c[0]), "+f"(c[1]), "+f"(c[2]), "+f"(c[3])
        : "r"(a[0]), "r"(a[1]), "r"(a[2]), "r"(a[3]),
          "r"(b[0]), "r"(b[1]));
}
__device__ __forceinline__ void cp16(uint32_t dst, const void* src) {
    asm volatile("cp.async.cg.shared.global [%0], [%1], 16;" :: "r"(dst), "l"(src));
}
__device__ __forceinline__ uint32_t smem_u32(const void* p) {
    return (uint32_t)__cvta_generic_to_shared(p);
}
__device__ __forceinline__ uint32_t h2u(__half2 h) {
    return *(uint32_t*)&h;
}

// ---------------- FP16 3-stage pipelined tensor-core GEMM ------------------
// C = A(MxK, half row-major) * B(KxN, k-pair-interleaved half2)
// OUTH: write half (intermediate) vs float (final output).
template<bool OUTH>
__global__ void __launch_bounds__(256, 2)
gemm_h(const __half* __restrict__ A, const uint32_t* __restrict__ Bg,
       void* __restrict__ Cv, int M, int N, int K, int ldc)
{
    // BM=128, BN=128, BK=32, WM=64, WN=32 -> MT=4, NT=4, 8 warps
    constexpr int MT = 4, NT = 4;
    constexpr int ABYTES = 128*80;       // 128 rows x (32+8 halves)=80B
    constexpr int BBYTES = 16*528;       // 16 kp rows x (128+4 u32)=528B
    constexpr int SMA = 3*ABYTES;        // 30720

    const int bm = blockIdx.y * 128;
    const int bn = blockIdx.x * 128;

    extern __shared__ char smem[];
    const uint32_t s_as = smem_u32(smem);
    const uint32_t s_bs = s_as + SMA;

    const int tid  = threadIdx.x;
    const int warp = tid >> 5;
    const int lane = tid & 31;
    const int lr   = lane >> 2;
    const int lc   = lane & 3;
    const int wm0  = (warp >> 2) * 64;   // WARPS_N = 4
    const int wn0  = (warp & 3) * 32;

    float acc[MT][NT][4];
    #pragma unroll
    for (int i = 0; i < MT; i++)
        #pragma unroll
        for (int j = 0; j < NT; j++)
            #pragma unroll
            for (int r = 0; r < 4; r++) acc[i][j][r] = 0.f;

    const int ntiles = K >> 5;           // K/32

    auto load_tile = [&](int kt, int buf) {
        const int k0 = kt * 32;
        #pragma unroll
        for (int i = tid; i < 128*4; i += 256) {
            int m = i >> 2, kq = i & 3;
            cp16(s_as + (uint32_t)(buf*ABYTES + m*80 + kq*16),
                 A + (size_t)(bm+m)*K + k0 + kq*8);
        }
        #pragma unroll
        for (int i = tid; i < 16*32; i += 256) {
            int kp = i >> 5, c = i & 31;
            cp16(s_bs + (uint32_t)(buf*BBYTES + kp*528 + c*16),
                 Bg + (size_t)((k0>>1) + kp)*N + bn + c*4);
        }
    };

    load_tile(0, 0);
    asm volatile("cp.async.commit_group;");
    if (ntiles > 1) {
        load_tile(1, 1);
        asm volatile("cp.async.commit_group;");
    }

    int buf = 0;
    for (int kt = 0; kt < ntiles; kt++) {
        if (kt + 1 < ntiles) asm volatile("cp.async.wait_group 1;");
        else                 asm volatile("cp.async.wait_group 0;");
        __syncthreads();

        const int nxt = kt + 2;
        if (nxt < ntiles) {
            load_tile(nxt, nxt - (nxt/3)*3);
            asm volatile("cp.async.commit_group;");
        }

        const uint32_t* AtU = (const uint32_t*)(smem + buf*ABYTES);
        const uint32_t* BtU = (const uint32_t*)(smem + SMA + buf*BBYTES);

        #pragma unroll
        for (int kk = 0; kk < 32; kk += 16) {
            uint32_t a[MT][4], b[NT][2];
            #pragma unroll
            for (int mt = 0; mt < MT; mt++) {
                int base = (wm0 + mt*16 + lr)*20 + (kk>>1) + lc;
                a[mt][0] = AtU[base];
                a[mt][1] = AtU[base + 160];
                a[mt][2] = AtU[base + 4];
                a[mt][3] = AtU[base + 164];
            }
            #pragma unroll
            for (int nt = 0; nt < NT; nt++) {
                int bb = ((kk>>1) + lc)*132 + wn0 + nt*8 + lr;
                b[nt][0] = BtU[bb];
                b[nt][1] = BtU[bb + 528];
            }
            #pragma unroll
            for (int mt = 0; mt < MT; mt++)
                #pragma unroll
                for (int nt = 0; nt < NT; nt++)
                    mma_f16(acc[mt][nt], a[mt], b[nt]);
        }
        buf = (buf == 2) ? 0 : buf + 1;
    }

    #pragma unroll
    for (int mt = 0; mt < MT; mt++) {
        int row0 = bm + wm0 + mt*16 + lr;
        #pragma unroll
        for (int nt = 0; nt < NT; nt++) {
            int col = bn + wn0 + nt*8 + 2*lc;
            if (OUTH) {
                __half2* Ch = (__half2*)Cv;
                Ch[((size_t)row0*ldc + col) >> 1]     = __floats2half2_rn(acc[mt][nt][0], acc[mt][nt][1]);
                Ch[((size_t)(row0+8)*ldc + col) >> 1] = __floats2half2_rn(acc[mt][nt][2], acc[mt][nt][3]);
            } else {
                float* Cf = (float*)Cv;
                *(float2*)(Cf + (size_t)row0*ldc + col)     = make_float2(acc[mt][nt][0], acc[mt][nt][1]);
                *(float2*)(Cf + (size_t)(row0+8)*ldc + col) = make_float2(acc[mt][nt][2], acc[mt][nt][3]);
            }
        }
    }
}

// ---------------------- fused flash attention (fp16) -----------------------
// Q,K: [bh][t][96] half.  V: key-pair interleaved [bh][t/2][64] half2.
__global__ void __launch_bounds__(256, 2)
flash_attn(const __half* __restrict__ Qg, const __half* __restrict__ Kg,
           const __half* __restrict__ Vg, __half* __restrict__ Yg, float scl)
{
    constexpr int QROWB = 208, VROWB = 272;
    constexpr int QB = 128*QROWB;          // 26624
    constexpr int KB = 64*QROWB;           // 13312 per buf
    constexpr int VB = 32*VROWB;           // 8704 per buf
    extern __shared__ char smc[];
    char* sQ = smc;
    char* sK = sQ + QB;
    char* sV = sK + 2*KB;
    char* sP = sV + 2*VB;
    const uint32_t uQ = smem_u32(sQ), uK = smem_u32(sK), uV = smem_u32(sV);

    const int qi = blockIdx.x, bh = blockIdx.y;
    const int tid = threadIdx.x, warp = tid >> 5, lane = tid & 31;
    const int lr = lane >> 2, lc = lane & 3;
    const int wm0 = warp * 16;

    const __half* Qp = Qg + (size_t)(bh*Tt + qi*128)*Dd;
    const __half* Kp = Kg + (size_t)bh*Tt*Dd;
    const uint32_t* Vp = (const uint32_t*)Vg + (size_t)bh*(Tt/2)*HS_;

    for (int i = tid; i < 128*12; i += 256) {
        int r = i/12, cq = i%12;
        cp16(uQ + (uint32_t)(r*QROWB + cq*16), Qp + (size_t)r*Dd + cq*8);
    }
    auto load_kv = [&](int j, int buf){
        const __half* kp = Kp + (size_t)j*64*Dd;
        for (int i = tid; i < 64*12; i += 256) {
            int r = i/12, cq = i%12;
            cp16(uK + (uint32_t)(buf*KB + r*QROWB + cq*16), kp + (size_t)r*Dd + cq*8);
        }
        const uint32_t* vp = Vp + (size_t)j*32*HS_;
        for (int i = tid; i < 32*16; i += 256) {
            int r = i>>4, cq = i&15;
            cp16(uV + (uint32_t)(buf*VB + r*VROWB + cq*16), vp + (size_t)r*HS_ + cq*4);
        }
    };
    load_kv(0, 0);
    asm volatile("cp.async.commit_group;");

    float oacc[8][4];
    #pragma unroll
    for (int n = 0; n < 8; n++)
        #pragma unroll
        for (int r = 0; r < 4; r++) oacc[n][r] = 0.f;
    float m_lo = -1e30f, m_hi = -1e30f, l_lo = 0.f, l_hi = 0.f;

    const int njt = 2*qi + 2;
    const int q_lo = qi*128 + wm0 + lr;
    const int q_hi = q_lo + 8;

    const uint32_t* sQu = (const uint32_t*)sQ;
    uint32_t* sPu = (uint32_t*)sP;

    for (int j = 0; j < njt; j++) {
        const int buf = j & 1;
        if (j + 1 < njt) {
            load_kv(j+1, buf^1);
            asm volatile("cp.async.commit_group;");
            asm volatile("cp.async.wait_group 1;");
        } else {
            asm volatile("cp.async.wait_group 0;");
        }
        __syncthreads();

        const uint32_t* sKu = (const uint32_t*)(sK + buf*KB);
        const uint32_t* sVu = (const uint32_t*)(sV + buf*VB);

        // S = Q @ K^T  (rows wm0..wm0+15, 64 cols), 6 k16-steps
        float sacc[8][4];
        #pragma unroll
        for (int n = 0; n < 8; n++)
            #pragma unroll
            for (int r = 0; r < 4; r++) sacc[n][r] = 0.f;

        #pragma unroll
        for (int kk = 0; kk < Dd; kk += 16) {
            uint32_t a[4], b[8][2];
            int ab = (wm0+lr)*52 + (kk>>1) + lc;
            a[0] = sQu[ab]; a[1] = sQu[ab + 8*52]; a[2] = sQu[ab + 4]; a[3] = sQu[ab + 8*52 + 4];
            #pragma unroll
            for (int n = 0; n < 8; n++) {
                int bb = (n*8+lr)*52 + (kk>>1) + lc;
                b[n][0] = sKu[bb];
                b[n][1] = sKu[bb + 4];
            }
            #pragma unroll
            for (int n = 0; n < 8; n++) mma_f16(sacc[n], a, b[n]);
        }

        const bool need_mask = (j >= 2*qi);
        float tmax_lo = -1e30f, tmax_hi = -1e30f;
        #pragma unroll
        for (int n = 0; n < 8; n++) {
            const int c0 = j*64 + n*8 + 2*lc;
            #pragma unroll
            for (int e = 0; e < 2; e++) {
                float slo = sacc[n][e]   * scl;
                float shi = sacc[n][2+e] * scl;
                if (need_mask) {
                    if (c0+e > q_lo) slo = -1e30f;
                    if (c0+e > q_hi) shi = -1e30f;
                }
                sacc[n][e]   = slo;
                sacc[n][2+e] = shi;
                tmax_lo = fmaxf(tmax_lo, slo);
                tmax_hi = fmaxf(tmax_hi, shi);
            }
        }
        tmax_lo = fmaxf(tmax_lo, __shfl_xor_sync(0xffffffffu, tmax_lo, 1));
        tmax_lo = fmaxf(tmax_lo, __shfl_xor_sync(0xffffffffu, tmax_lo, 2));
        tmax_hi = fmaxf(tmax_hi, __shfl_xor_sync(0xffffffffu, tmax_hi, 1));
        tmax_hi = fmaxf(tmax_hi, __shfl_xor_sync(0xffffffffu, tmax_hi, 2));

        const float mn_lo = fmaxf(m_lo, tmax_lo);
        const float mn_hi = fmaxf(m_hi, tmax_hi);
        const float al_lo = __expf(m_lo - mn_lo);
        const float al_hi = __expf(m_hi - mn_hi);
        m_lo = mn_lo; m_hi = mn_hi;

        float sum_lo = 0.f, sum_hi = 0.f;
        #pragma unroll
        for (int n = 0; n < 8; n++) {
            #pragma unroll
            for (int e = 0; e < 2; e++) {
                float plo = __expf(sacc[n][e]   - mn_lo);
                float phi = __expf(sacc[n][2+e] - mn_hi);
                sacc[n][e]   = plo;
                sacc[n][2+e] = phi;
                sum_lo += plo;
                sum_hi += phi;
            }
        }
        sum_lo += __shfl_xor_sync(0xffffffffu, sum_lo, 1);
        sum_lo += __shfl_xor_sync(0xffffffffu, sum_lo, 2);
        sum_hi += __shfl_xor_sync(0xffffffffu, sum_hi, 1);
        sum_hi += __shfl_xor_sync(0xffffffffu, sum_hi, 2);
        l_lo = l_lo*al_lo + sum_lo;
        l_hi = l_hi*al_hi + sum_hi;

        #pragma unroll
        for (int n = 0; n < 8; n++) {
            oacc[n][0] *= al_lo; oacc[n][1] *= al_lo;
            oacc[n][2] *= al_hi; oacc[n][3] *= al_hi;
        }

        // P -> smem as half2 (warp-private rows)
        #pragma unroll
        for (int n = 0; n < 8; n++) {
            sPu[(wm0+lr)*36   + n*4 + lc] = h2u(__floats2half2_rn(sacc[n][0], sacc[n][1]));
            sPu[(wm0+lr+8)*36 + n*4 + lc] = h2u(__floats2half2_rn(sacc[n][2], sacc[n][3]));
        }
        __syncwarp();

        // O += P @ V   (4 k16-steps over keys)
        #pragma unroll
        for (int kk = 0; kk < 64; kk += 16) {
            uint32_t a[4], b[8][2];
            int ab = (wm0+lr)*36 + (kk>>1) + lc;
            a[0] = sPu[ab]; a[1] = sPu[ab + 8*36]; a[2] = sPu[ab + 4]; a[3] = sPu[ab + 8*36 + 4];
            #pragma unroll
            for (int n = 0; n < 8; n++) {
                int bb = ((kk>>1) + lc)*68 + n*8 + lr;
                b[n][0] = sVu[bb];
                b[n][1] = sVu[bb + 4*68];
            }
            #pragma unroll
            for (int n = 0; n < 8; n++) mma_f16(oacc[n], a, b[n]);
        }
        __syncthreads();
    }

    // epilogue: Y (B,T,H*64) half
    const int b = bh >> 4, h = bh & 15;
    const float inv_lo = 1.f / l_lo, inv_hi = 1.f / l_hi;
    uint32_t* Yu = (uint32_t*)Yg;
    const size_t r0 = (size_t)(b*Tt + qi*128 + wm0 + lr)*512 + h*32;
    #pragma unroll
    for (int n = 0; n < 8; n++) {
        Yu[r0 + n*4 + lc]         = h2u(__floats2half2_rn(oacc[n][0]*inv_lo, oacc[n][1]*inv_lo));
        Yu[r0 + 8*512 + n*4 + lc] = h2u(__floats2half2_rn(oacc[n][2]*inv_hi, oacc[n][3]*inv_hi));
    }
}

// ------------------------- conversion kernels ------------------------------
__global__ void round_h(const float2* __restrict__ src, __half2* __restrict__ dst, int n2)
{
    for (int i = blockIdx.x*blockDim.x + threadIdx.x; i < n2;
         i += gridDim.x*blockDim.x) {
        float2 v = src[i];
        dst[i] = __floats2half2_rn(v.x, v.y);
    }
}

// interleave W[K][N] f32 -> Wp[k/2][ldN] half2 at column offset off
__global__ void wint(const float* __restrict__ W, __half2* __restrict__ dst,
                     int K2, int N, int ldN, int off)
{
    long long n = (long long)K2*N;
    for (long long i = (long long)blockIdx.x*blockDim.x + threadIdx.x; i < n;
         i += (long long)gridDim.x*blockDim.x) {
        int kp = (int)(i / N);
        int c  = (int)(i % N);
        dst[(size_t)kp*ldN + off + c] =
            __floats2half2_rn(W[(size_t)(2*kp)*N + c], W[(size_t)(2*kp+1)*N + c]);
    }
}

// ------------------------- small-N GEMM (k_R, N=32) ------------------------
__global__ void gemm_n32(const __half* __restrict__ A, const float* __restrict__ Bw,
                         float* __restrict__ Cm, int M, int K)
{
    int gw   = (blockIdx.x * blockDim.x + threadIdx.x) >> 5;
    int lane = threadIdx.x & 31;
    if (gw >= M) return;
    const __half* a = A + (size_t)gw * K;
    float acc = 0.f;
    #pragma unroll 8
    for (int k = 0; k < K; k++)
        acc += __half2float(a[k]) * Bw[k*32 + lane];
    Cm[(size_t)gw*32 + lane] = acc;
}

// --------------------- assemble Q/K/V with RoPE scale ----------------------
__constant__ float c_inv[16] = {
    1.0f, 0.5623413251903491f, 0.31622776601683794f, 0.17782794100389228f,
    0.1f, 0.05623413251903491f, 0.031622776601683794f, 0.017782794100389228f,
    0.01f, 0.005623413251903491f, 0.0031622776601683794f, 0.0017782794100389228f,
    0.001f, 0.0005623413251903491f, 0.00031622776601683794f, 0.00017782794100389228f
};

__global__ void assemble_qkv(const __half* __restrict__ qCR,
                             const __half* __restrict__ kCv,
                             const float* __restrict__ kR,
                             __half* __restrict__ Q, __half* __restrict__ K,
                             __half* __restrict__ V)
{
    const long long total = (long long)BH * Tt * Dd;
    for (long long idx = (long long)blockIdx.x * blockDim.x + threadIdx.x;
         idx < total; idx += (long long)gridDim.x * blockDim.x)
    {
        int d = (int)(idx % Dd);
        long long r = idx / Dd;            // (b,h,t)
        int t = (int)(r % Tt);
        long long r2 = r / Tt;             // (b,h)
        int h = (int)(r2 % Hh);
        int b = (int)(r2 / Hh);
        long long bt = (long long)b * Tt + t;

        float qv, kv;
        if (d < HS_) {
            qv = __half2float(qCR[bt * 1536 + h * HS_ + d]);
            kv = __half2float(kCv[bt * 2048 + h * HS_ + d]);
            // V key-pair interleaved: [bh][t/2][d][2]
            V[((r2 * Tt + t) >> 1) * 128 + d*2 + (t & 1)] =
                kCv[bt * 2048 + 1024 + h * HS_ + d];
        } else {
            int j  = d - HS_;
            int fi = j & 15;
            float ang = (float)t * c_inv[fi];
            float s_, co;
            sincosf(ang, &s_, &co);
            float sc = co + s_;
            qv = __half2float(qCR[bt * 1536 + 1024 + h * DHR_ + j]) * sc;
            kv = kR[bt * 32 + j] * sc;
        }
        Q[idx] = __float2half_rn(qv);
        K[idx] = __float2half_rn(kv);
    }
}

// ---------------------------------------------------------------------------
extern "C" void kernel_launch(void* const* d_in, const int* in_sizes, int n_in,
                              void* d_out, int out_size)
{
    const float* x     = (const float*)d_in[0];
    const float* W_DQ  = (const float*)d_in[1];
    const float* W_UQ  = (const float*)d_in[2];
    const float* W_DKV = (const float*)d_in[3];
    const float* W_UK  = (const float*)d_in[4];
    const float* W_UV  = (const float*)d_in[5];
    const float* W_QR  = (const float*)d_in[6];
    const float* W_KR  = (const float*)d_in[7];
    const float* W_O   = (const float*)d_in[8];
    float* out = (float*)d_out;

    __half *xr,*cQ,*qCR,*cKV,*kCv,*Q,*K,*V,*Y,*wdq,*wuqr,*wdkv,*wukv,*wo;
    float *kR;
    cudaGetSymbolAddress((void**)&xr,  g_x);
    cudaGetSymbolAddress((void**)&cQ,  g_cQ);
    cudaGetSymbolAddress((void**)&qCR, g_qCR);
    cudaGetSymbolAddress((void**)&cKV, g_cKV);
    cudaGetSymbolAddress((void**)&kCv, g_kCv);
    cudaGetSymbolAddress((void**)&kR,  g_kR);
    cudaGetSymbolAddress((void**)&Q,   g_Q);
    cudaGetSymbolAddress((void**)&K,   g_K);
    cudaGetSymbolAddress((void**)&V,   g_V);
    cudaGetSymbolAddress((void**)&Y,   g_Y);
    cudaGetSymbolAddress((void**)&wdq, g_wdq);
    cudaGetSymbolAddress((void**)&wuqr,g_wuqr);
    cudaGetSymbolAddress((void**)&wdkv,g_wdkv);
    cudaGetSymbolAddress((void**)&wukv,g_wukv);
    cudaGetSymbolAddress((void**)&wo,  g_wo);

    const int SM_H  = 3*(128*80 + 16*528);                       // 56064
    const int SM_FL = 128*208 + 2*64*208 + 2*32*272 + 128*144;   // 89088

    cudaFuncSetAttribute(gemm_h<true>,  cudaFuncAttributeMaxDynamicSharedMemorySize, SM_H);
    cudaFuncSetAttribute(gemm_h<false>, cudaFuncAttributeMaxDynamicSharedMemorySize, SM_H);
    cudaFuncSetAttribute(flash_attn,    cudaFuncAttributeMaxDynamicSharedMemorySize, SM_FL);

    // launches 0-4: conversions needed by GEMM1/2/3 (GEMM1 = launch index 5 for ncu)
    round_h<<<2048,256>>>((const float2*)x, (__half2*)xr, MM*Cc_/2);
    wint<<<1024,256>>>(W_DQ,  (__half2*)wdq,  512,  4096, 4096, 0);
    wint<<<1024,256>>>(W_UQ,  (__half2*)wuqr, 2048, 1024, 1536, 0);
    wint<<<1024,256>>>(W_QR,  (__half2*)wuqr, 2048, 512,  1536, 1024);
    wint<<<256, 256>>>(W_DKV, (__half2*)wdkv, 512,  256,  256,  0);

    // 5. cQ = x @ W_DQ              (8192, 4096, 1024)
    gemm_h<true><<<dim3(4096/128, MM/128), 256, SM_H>>>(
        xr, (const uint32_t*)wdq, cQ, MM, 4096, 1024, 4096);
    // 6. qCR = cQ @ [W_UQ|W_QR]     (8192, 1536, 4096)
    gemm_h<true><<<dim3(1536/128, MM/128), 256, SM_H>>>(
        cQ, (const uint32_t*)wuqr, qCR, MM, 1536, 4096, 1536);
    // 7. cKV = x @ W_DKV            (8192, 256, 1024)
    gemm_h<true><<<dim3(256/128, MM/128), 256, SM_H>>>(
        xr, (const uint32_t*)wdkv, cKV, MM, 256, 1024, 256);

    wint<<<256, 256>>>(W_UK, (__half2*)wukv, 128, 1024, 2048, 0);
    wint<<<256, 256>>>(W_UV, (__half2*)wukv, 128, 1024, 2048, 1024);

    // 10. kCv = cKV @ [W_UK|W_UV]   (8192, 2048, 256)
    gemm_h<true><<<dim3(2048/128, MM/128), 256, SM_H>>>(
        cKV, (const uint32_t*)wukv, kCv, MM, 2048, 256, 2048);
    // 11. kR = x @ W_KR             (8192, 32, 1024), W_KR read as fp32 direct
    gemm_n32<<<(MM*32)/256, 256>>>(xr, W_KR, kR, MM, 1024);

    // 12. assemble Q/K/V with RoPE scale (half outputs, V interleaved)
    {
        long long total = (long long)BH * Tt * Dd;
        int blocks = (int)((total + 255) / 256);
        assemble_qkv<<<blocks, 256>>>(qCR, kCv, kR, Q, K, V);
    }

    // 13. fused flash attention -> Y (B,T,H*64) half
    flash_attn<<<dim3(16, BH), 256, SM_FL>>>(Q, K, V, Y, 1.0f/sqrtf((float)Dd));

    // 14. wo conversion, 15. out = Y @ W_O (8192, 1024, 1024), fp32 out
    wint<<<512, 256>>>(W_O, (__half2*)wo, 512, 1024, 1024, 0);
    gemm_h<false><<<dim3(1024/128, MM/128), 256, SM_H>>>(
        Y, (const uint32_t*)wo, out, MM, 1024, 1024, 1024);
}